// round 1
// baseline (speedup 1.0000x reference)
#include <cuda_runtime.h>
#include <math.h>

#define BATCH 4
#define SEQ 2048
#define DIM 1024      // in_shape == hidden_units == 1024
#define HEADS 16
#define DK 64
#define M_TOTAL (BATCH * SEQ)   // 8192

// Scratch: Q, K, V, CTX  (each 8192 x 1024 fp32 = 32 MB)
__device__ float g_Q[M_TOTAL * DIM];
__device__ float g_K[M_TOTAL * DIM];
__device__ float g_V[M_TOTAL * DIM];
__device__ float g_CTX[M_TOTAL * DIM];

// ---------------------------------------------------------------------------
// SGEMM: Y[m][n] = sum_k X[m][k] * W[n][k] + bias[n]
// M = 8192, N = 1024, K = 1024.  X row-major [M,K], W row-major [N,K].
// BM=128, BN=128, BK=16, 256 threads, 8x8 register tile per thread.
// ---------------------------------------------------------------------------
#define BM 128
#define BN 128
#define BK 16
#define PAD 4   // smem pad (4 floats = 16B, keeps float4 alignment)

__global__ void __launch_bounds__(256, 2)
sgemm_bias_kernel(const float* __restrict__ X, const float* __restrict__ W,
                  const float* __restrict__ bias, float* __restrict__ Y)
{
    __shared__ float As[BK][BM + PAD];
    __shared__ float Bs[BK][BN + PAD];

    const int bm = blockIdx.y * BM;
    const int bn = blockIdx.x * BN;
    const int tid = threadIdx.x;

    const int tr = (tid / 16) * 8;   // row within tile: 0..120
    const int tc = (tid % 16) * 8;   // col within tile: 0..120

    float acc[8][8];
#pragma unroll
    for (int i = 0; i < 8; i++)
#pragma unroll
        for (int j = 0; j < 8; j++) acc[i][j] = 0.f;

    for (int k0 = 0; k0 < DIM; k0 += BK) {
        // Load A tile (128 rows x 16 cols) and B tile, transposed into smem.
        // 128*16 floats = 512 float4 per tile; 256 threads -> 2 float4 each.
#pragma unroll
        for (int l = 0; l < 2; l++) {
            int idx = tid + l * 256;        // 0..511
            int row = idx >> 2;             // 0..127
            int c4  = (idx & 3) * 4;        // 0,4,8,12
            float4 va = *(const float4*)(X + (size_t)(bm + row) * DIM + k0 + c4);
            As[c4 + 0][row] = va.x;
            As[c4 + 1][row] = va.y;
            As[c4 + 2][row] = va.z;
            As[c4 + 3][row] = va.w;
            float4 vb = *(const float4*)(W + (size_t)(bn + row) * DIM + k0 + c4);
            Bs[c4 + 0][row] = vb.x;
            Bs[c4 + 1][row] = vb.y;
            Bs[c4 + 2][row] = vb.z;
            Bs[c4 + 3][row] = vb.w;
        }
        __syncthreads();

#pragma unroll
        for (int kk = 0; kk < BK; kk++) {
            float a[8], b[8];
            float4 a0 = *(const float4*)&As[kk][tr];
            float4 a1 = *(const float4*)&As[kk][tr + 4];
            a[0]=a0.x; a[1]=a0.y; a[2]=a0.z; a[3]=a0.w;
            a[4]=a1.x; a[5]=a1.y; a[6]=a1.z; a[7]=a1.w;
            float4 b0 = *(const float4*)&Bs[kk][tc];
            float4 b1 = *(const float4*)&Bs[kk][tc + 4];
            b[0]=b0.x; b[1]=b0.y; b[2]=b0.z; b[3]=b0.w;
            b[4]=b1.x; b[5]=b1.y; b[6]=b1.z; b[7]=b1.w;
#pragma unroll
            for (int i = 0; i < 8; i++)
#pragma unroll
                for (int j = 0; j < 8; j++)
                    acc[i][j] = fmaf(a[i], b[j], acc[i][j]);
        }
        __syncthreads();
    }

    // Epilogue: add bias, vectorized store.
    float4 bia0 = *(const float4*)(bias + bn + tc);
    float4 bia1 = *(const float4*)(bias + bn + tc + 4);
#pragma unroll
    for (int i = 0; i < 8; i++) {
        float* yr = Y + (size_t)(bm + tr + i) * DIM + bn + tc;
        float4 o0, o1;
        o0.x = acc[i][0] + bia0.x; o0.y = acc[i][1] + bia0.y;
        o0.z = acc[i][2] + bia0.z; o0.w = acc[i][3] + bia0.w;
        o1.x = acc[i][4] + bia1.x; o1.y = acc[i][5] + bia1.y;
        o1.z = acc[i][6] + bia1.z; o1.w = acc[i][7] + bia1.w;
        *(float4*)yr       = o0;
        *(float4*)(yr + 4) = o1;
    }
}

// ---------------------------------------------------------------------------
// Flash-attention style kernel.
// Grid: (S/64 query tiles, HEADS, BATCH). 256 threads (16x16 layout).
// Each thread owns a 4x4 tile of the 64x64 (rows=queries, cols=dk) output,
// and the matching 4x4 tile of each 64x64 score block.
// Layout of Q/K/V/CTX: [(b*SEQ + s)*HEADS + h]*DK + d   (row stride 1024)
// ---------------------------------------------------------------------------
#define BQ 64
#define BKV 64
#define ATT_LDP (DK + 1)     // 65, padded row
#define ATT_SMEM_FLOATS (4 * BQ * ATT_LDP)
#define ATT_SMEM_BYTES (ATT_SMEM_FLOATS * 4)

__global__ void __launch_bounds__(256, 3)
attn_kernel(const float* __restrict__ Qg, const float* __restrict__ Kg,
            const float* __restrict__ Vg, float* __restrict__ Cg)
{
    extern __shared__ float smem[];
    float* Qs = smem;                      // [BQ][65]
    float* Ks = Qs + BQ * ATT_LDP;         // [BKV][65]
    float* Vs = Ks + BKV * ATT_LDP;        // [BKV][65]
    float* Ps = Vs + BKV * ATT_LDP;        // [BQ][65]

    const int qt = blockIdx.x;
    const int h  = blockIdx.y;
    const int b  = blockIdx.z;
    const int tid = threadIdx.x;
    const int ty = tid / 16, tx = tid % 16;
    const int r0 = ty * 4, c0 = tx * 4;
    const float scale = 0.125f;   // 1/sqrt(64)

    // Load Q tile (64 rows x 64 floats), row stride in gmem = HEADS*DK = 1024
    const float* Qbase = Qg + (((size_t)b * SEQ + (size_t)qt * BQ) * HEADS + h) * DK;
    for (int j = tid; j < BQ * 16; j += 256) {
        int row = j >> 4;
        int c4  = (j & 15) * 4;
        float4 v = *(const float4*)(Qbase + (size_t)row * (HEADS * DK) + c4);
        Qs[row * ATT_LDP + c4 + 0] = v.x;
        Qs[row * ATT_LDP + c4 + 1] = v.y;
        Qs[row * ATT_LDP + c4 + 2] = v.z;
        Qs[row * ATT_LDP + c4 + 3] = v.w;
    }

    float m_i[4], l_i[4], O[4][4];
#pragma unroll
    for (int i = 0; i < 4; i++) {
        m_i[i] = -INFINITY; l_i[i] = 0.f;
#pragma unroll
        for (int j = 0; j < 4; j++) O[i][j] = 0.f;
    }

    for (int kt = 0; kt < SEQ / BKV; kt++) {
        __syncthreads();   // prior iteration done reading Ks/Vs; Q load fenced below
        const float* Kbase = Kg + (((size_t)b * SEQ + (size_t)kt * BKV) * HEADS + h) * DK;
        const float* Vbase = Vg + (((size_t)b * SEQ + (size_t)kt * BKV) * HEADS + h) * DK;
        for (int j = tid; j < BKV * 16; j += 256) {
            int row = j >> 4;
            int c4  = (j & 15) * 4;
            float4 kv = *(const float4*)(Kbase + (size_t)row * (HEADS * DK) + c4);
            Ks[row * ATT_LDP + c4 + 0] = kv.x;
            Ks[row * ATT_LDP + c4 + 1] = kv.y;
            Ks[row * ATT_LDP + c4 + 2] = kv.z;
            Ks[row * ATT_LDP + c4 + 3] = kv.w;
            float4 vv = *(const float4*)(Vbase + (size_t)row * (HEADS * DK) + c4);
            Vs[row * ATT_LDP + c4 + 0] = vv.x;
            Vs[row * ATT_LDP + c4 + 1] = vv.y;
            Vs[row * ATT_LDP + c4 + 2] = vv.z;
            Vs[row * ATT_LDP + c4 + 3] = vv.w;
        }
        __syncthreads();

        // S = Q @ K^T for this 64x64 block (each thread: 4x4)
        float s[4][4];
#pragma unroll
        for (int i = 0; i < 4; i++)
#pragma unroll
            for (int j = 0; j < 4; j++) s[i][j] = 0.f;

#pragma unroll 4
        for (int d = 0; d < DK; d++) {
            float a[4], bb[4];
#pragma unroll
            for (int i = 0; i < 4; i++) a[i]  = Qs[(r0 + i) * ATT_LDP + d];
#pragma unroll
            for (int j = 0; j < 4; j++) bb[j] = Ks[(c0 + j) * ATT_LDP + d];
#pragma unroll
            for (int i = 0; i < 4; i++)
#pragma unroll
                for (int j = 0; j < 4; j++)
                    s[i][j] = fmaf(a[i], bb[j], s[i][j]);
        }

        // Online softmax per row (row owned by 16 threads along tx = lane%16)
#pragma unroll
        for (int i = 0; i < 4; i++) {
            float mx = -INFINITY;
#pragma unroll
            for (int j = 0; j < 4; j++) {
                s[i][j] *= scale;
                mx = fmaxf(mx, s[i][j]);
            }
#pragma unroll
            for (int o = 8; o >= 1; o >>= 1)
                mx = fmaxf(mx, __shfl_xor_sync(0xffffffffu, mx, o));
            float m_new = fmaxf(m_i[i], mx);
            float corr = __expf(m_i[i] - m_new);
            float rs = 0.f;
#pragma unroll
            for (int j = 0; j < 4; j++) {
                s[i][j] = __expf(s[i][j] - m_new);
                rs += s[i][j];
            }
#pragma unroll
            for (int o = 8; o >= 1; o >>= 1)
                rs += __shfl_xor_sync(0xffffffffu, rs, o);
            l_i[i] = l_i[i] * corr + rs;
            m_i[i] = m_new;
#pragma unroll
            for (int j = 0; j < 4; j++) {
                O[i][j] *= corr;
                Ps[(r0 + i) * ATT_LDP + c0 + j] = s[i][j];
            }
        }
        __syncthreads();

        // O += P @ V  (P: 64x64 in smem, V: 64x64 in smem)
#pragma unroll 4
        for (int k = 0; k < BKV; k++) {
            float p[4], v[4];
#pragma unroll
            for (int i = 0; i < 4; i++) p[i] = Ps[(r0 + i) * ATT_LDP + k];
#pragma unroll
            for (int j = 0; j < 4; j++) v[j] = Vs[k * ATT_LDP + c0 + j];
#pragma unroll
            for (int i = 0; i < 4; i++)
#pragma unroll
                for (int j = 0; j < 4; j++)
                    O[i][j] = fmaf(p[i], v[j], O[i][j]);
        }
    }

    // Normalize and write ctx: same layout as Q
    float* Cbase = Cg + (((size_t)b * SEQ + (size_t)qt * BQ) * HEADS + h) * DK;
#pragma unroll
    for (int i = 0; i < 4; i++) {
        float inv_l = 1.f / l_i[i];
        float* cr = Cbase + (size_t)(r0 + i) * (HEADS * DK) + c0;
        float4 o;
        o.x = O[i][0] * inv_l; o.y = O[i][1] * inv_l;
        o.z = O[i][2] * inv_l; o.w = O[i][3] * inv_l;
        *(float4*)cr = o;
    }
}

// ---------------------------------------------------------------------------
// Launch
// ---------------------------------------------------------------------------
extern "C" void kernel_launch(void* const* d_in, const int* in_sizes, int n_in,
                              void* d_out, int out_size)
{
    const float* X  = (const float*)d_in[0];
    const float* Wq = (const float*)d_in[1];
    const float* bq = (const float*)d_in[2];
    const float* Wk = (const float*)d_in[3];
    const float* bk = (const float*)d_in[4];
    const float* Wv = (const float*)d_in[5];
    const float* bv = (const float*)d_in[6];
    const float* Wo = (const float*)d_in[7];
    const float* bo = (const float*)d_in[8];

    float *Qp, *Kp, *Vp, *Cp;
    cudaGetSymbolAddress((void**)&Qp, g_Q);
    cudaGetSymbolAddress((void**)&Kp, g_K);
    cudaGetSymbolAddress((void**)&Vp, g_V);
    cudaGetSymbolAddress((void**)&Cp, g_CTX);

    dim3 ggrid(DIM / BN, M_TOTAL / BM);   // (8, 64)

    sgemm_bias_kernel<<<ggrid, 256>>>(X, Wq, bq, Qp);
    sgemm_bias_kernel<<<ggrid, 256>>>(X, Wk, bk, Kp);
    sgemm_bias_kernel<<<ggrid, 256>>>(X, Wv, bv, Vp);

    cudaFuncSetAttribute(attn_kernel,
                         cudaFuncAttributeMaxDynamicSharedMemorySize,
                         ATT_SMEM_BYTES);
    attn_kernel<<<dim3(SEQ / BQ, HEADS, BATCH), 256, ATT_SMEM_BYTES>>>(Qp, Kp, Vp, Cp);

    sgemm_bias_kernel<<<ggrid, 256>>>(Cp, Wo, bo, (float*)d_out);
}

// round 3
// speedup vs baseline: 1.4033x; 1.4033x over previous
#include <cuda_runtime.h>
#include <cstdint>
#include <math.h>

#define BATCH 4
#define SEQ 2048
#define DIM 1024
#define HEADS 16
#define DK 64
#define M_TOTAL (BATCH * SEQ)   // 8192

// Scratch buffers (device globals; no allocation allowed)
__device__ float g_Q[M_TOTAL * DIM];
__device__ float g_K[M_TOTAL * DIM];
__device__ float g_V[M_TOTAL * DIM];
__device__ float g_CTX[M_TOTAL * DIM];

// ===========================================================================
// Helpers
// ===========================================================================
__device__ __forceinline__ uint32_t f2tf32(float x) {
    uint32_t r;
    asm("cvt.rna.tf32.f32 %0, %1;" : "=r"(r) : "f"(x));
    return r;
}

__device__ __forceinline__ void mma1688(float* d, const uint32_t* a, const uint32_t* b) {
    asm volatile(
        "mma.sync.aligned.m16n8k8.row.col.f32.tf32.tf32.f32 "
        "{%0,%1,%2,%3}, {%4,%5,%6,%7}, {%8,%9}, {%0,%1,%2,%3};"
        : "+f"(d[0]), "+f"(d[1]), "+f"(d[2]), "+f"(d[3])
        : "r"(a[0]), "r"(a[1]), "r"(a[2]), "r"(a[3]), "r"(b[0]), "r"(b[1]));
}

// ===========================================================================
// tf32 tensor-core GEMM: Y[m][n] = sum_k X[m][k]*W[n][k] + bias[n]
// M=8192, N=1024, K=1024. Tile 128x128, BK=32, double-buffered cp.async.
// 256 threads = 8 warps in a 2x4 grid; each warp computes 64x32 via
// 4x4 tiles of mma.sync.m16n8k8 (tf32), cvt.rna on fragment load.
// Smem rows padded to 36 floats -> conflict-free fragment gathers.
// ===========================================================================
#define TBM 128
#define TBN 128
#define TBK 32
#define LDS_ROW 36                      // floats per smem row (32 + 4 pad)
#define MAT_FLOATS (TBM * LDS_ROW)      // 4608 floats per matrix per stage
#define G_SMEM_BYTES (2 * 2 * MAT_FLOATS * 4)   // 73728

__global__ void __launch_bounds__(256, 2)
gemm_tc_kernel(const float* __restrict__ X, const float* __restrict__ W,
               const float* __restrict__ bias, float* __restrict__ Y)
{
    extern __shared__ float smem[];
    // layout: As[2][128][36], Bs[2][128][36]
    float* As = smem;
    float* Bs = smem + 2 * MAT_FLOATS;

    const int tid = threadIdx.x;
    const int wid = tid >> 5;
    const int lane = tid & 31;
    const int bm = blockIdx.y * TBM;
    const int bn = blockIdx.x * TBN;

    const int wm = (wid >> 2) * 64;     // warp m offset: 0 or 64
    const int wn = (wid & 3) * 32;      // warp n offset: 0,32,64,96

    const int lr = lane >> 2;           // 0..7
    const int lc = lane & 3;            // 0..3

    float acc[4][4][4];
#pragma unroll
    for (int i = 0; i < 4; i++)
#pragma unroll
        for (int j = 0; j < 4; j++)
#pragma unroll
            for (int r = 0; r < 4; r++) acc[i][j][r] = 0.f;

    // -------- async stage loader: 1024 float4 for A + 1024 for B --------
    auto issue_stage = [&](int kt, int buf) {
        const int k0 = kt * TBK;
        float* a_dst = As + buf * MAT_FLOATS;
        float* b_dst = Bs + buf * MAT_FLOATS;
#pragma unroll
        for (int l = 0; l < 4; l++) {            // A: 256 thr x 4 = 1024 float4
            int idx = tid + l * 256;
            int row = idx >> 3;
            int seg = (idx & 7) * 4;
            const float* src = X + (size_t)(bm + row) * DIM + k0 + seg;
            uint32_t dst;
            asm("{ .reg .u64 t; cvta.to.shared.u64 t, %1; cvt.u32.u64 %0, t; }"
                : "=r"(dst) : "l"(a_dst + row * LDS_ROW + seg));
            asm volatile("cp.async.cg.shared.global [%0], [%1], 16;" :: "r"(dst), "l"(src));
        }
#pragma unroll
        for (int l = 0; l < 4; l++) {            // B
            int idx = tid + l * 256;
            int row = idx >> 3;
            int seg = (idx & 7) * 4;
            const float* src = W + (size_t)(bn + row) * DIM + k0 + seg;
            uint32_t dst;
            asm("{ .reg .u64 t; cvta.to.shared.u64 t, %1; cvt.u32.u64 %0, t; }"
                : "=r"(dst) : "l"(b_dst + row * LDS_ROW + seg));
            asm volatile("cp.async.cg.shared.global [%0], [%1], 16;" :: "r"(dst), "l"(src));
        }
        asm volatile("cp.async.commit_group;" ::: "memory");
    };

    const int n_kt = DIM / TBK;   // 32
    issue_stage(0, 0);

    for (int kt = 0; kt < n_kt; kt++) {
        if (kt + 1 < n_kt) {
            issue_stage(kt + 1, (kt + 1) & 1);
            asm volatile("cp.async.wait_group 1;" ::: "memory");
        } else {
            asm volatile("cp.async.wait_group 0;" ::: "memory");
        }
        __syncthreads();

        const float* a_s = As + (kt & 1) * MAT_FLOATS;
        const float* b_s = Bs + (kt & 1) * MAT_FLOATS;

#pragma unroll
        for (int ks = 0; ks < 4; ks++) {
            const int k = ks * 8 + lc;
            uint32_t af[4][4];
#pragma unroll
            for (int mt = 0; mt < 4; mt++) {
                const float* p = a_s + (wm + mt * 16 + lr) * LDS_ROW + k;
                af[mt][0] = f2tf32(p[0]);
                af[mt][1] = f2tf32(p[8 * LDS_ROW]);
                af[mt][2] = f2tf32(p[4]);
                af[mt][3] = f2tf32(p[8 * LDS_ROW + 4]);
            }
            uint32_t bf[4][2];
#pragma unroll
            for (int nt = 0; nt < 4; nt++) {
                const float* p = b_s + (wn + nt * 8 + lr) * LDS_ROW + k;
                bf[nt][0] = f2tf32(p[0]);
                bf[nt][1] = f2tf32(p[4]);
            }
#pragma unroll
            for (int mt = 0; mt < 4; mt++)
#pragma unroll
                for (int nt = 0; nt < 4; nt++)
                    mma1688(acc[mt][nt], af[mt], bf[nt]);
        }
        __syncthreads();
    }

    // -------- epilogue: bias + store (float2 per fragment row) --------
#pragma unroll
    for (int mt = 0; mt < 4; mt++) {
#pragma unroll
        for (int nt = 0; nt < 4; nt++) {
            const int row = bm + wm + mt * 16 + lr;
            const int col = bn + wn + nt * 8 + lc * 2;
            float2 bv = *(const float2*)(bias + col);
            float2 o0, o1;
            o0.x = acc[mt][nt][0] + bv.x;
            o0.y = acc[mt][nt][1] + bv.y;
            o1.x = acc[mt][nt][2] + bv.x;
            o1.y = acc[mt][nt][3] + bv.y;
            *(float2*)(Y + (size_t)row * DIM + col)       = o0;
            *(float2*)(Y + (size_t)(row + 8) * DIM + col) = o1;
        }
    }
}

// ===========================================================================
// Flash-attention kernel (fp32) — unchanged from the passing R0 version.
// ===========================================================================
#define BQ 64
#define BKV 64
#define ATT_LDP (DK + 1)
#define ATT_SMEM_FLOATS (4 * BQ * ATT_LDP)
#define ATT_SMEM_BYTES (ATT_SMEM_FLOATS * 4)

__global__ void __launch_bounds__(256, 3)
attn_kernel(const float* __restrict__ Qg, const float* __restrict__ Kg,
            const float* __restrict__ Vg, float* __restrict__ Cg)
{
    extern __shared__ float smemf[];
    float* Qs = smemf;
    float* Ks = Qs + BQ * ATT_LDP;
    float* Vs = Ks + BKV * ATT_LDP;
    float* Ps = Vs + BKV * ATT_LDP;

    const int qt = blockIdx.x;
    const int h  = blockIdx.y;
    const int b  = blockIdx.z;
    const int tid = threadIdx.x;
    const int ty = tid / 16, tx = tid % 16;
    const int r0 = ty * 4, c0 = tx * 4;
    const float scale = 0.125f;

    const float* Qbase = Qg + (((size_t)b * SEQ + (size_t)qt * BQ) * HEADS + h) * DK;
    for (int j = tid; j < BQ * 16; j += 256) {
        int row = j >> 4;
        int c4  = (j & 15) * 4;
        float4 v = *(const float4*)(Qbase + (size_t)row * (HEADS * DK) + c4);
        Qs[row * ATT_LDP + c4 + 0] = v.x;
        Qs[row * ATT_LDP + c4 + 1] = v.y;
        Qs[row * ATT_LDP + c4 + 2] = v.z;
        Qs[row * ATT_LDP + c4 + 3] = v.w;
    }

    float m_i[4], l_i[4], O[4][4];
#pragma unroll
    for (int i = 0; i < 4; i++) {
        m_i[i] = -INFINITY; l_i[i] = 0.f;
#pragma unroll
        for (int j = 0; j < 4; j++) O[i][j] = 0.f;
    }

    for (int kt = 0; kt < SEQ / BKV; kt++) {
        __syncthreads();
        const float* Kbase = Kg + (((size_t)b * SEQ + (size_t)kt * BKV) * HEADS + h) * DK;
        const float* Vbase = Vg + (((size_t)b * SEQ + (size_t)kt * BKV) * HEADS + h) * DK;
        for (int j = tid; j < BKV * 16; j += 256) {
            int row = j >> 4;
            int c4  = (j & 15) * 4;
            float4 kv = *(const float4*)(Kbase + (size_t)row * (HEADS * DK) + c4);
            Ks[row * ATT_LDP + c4 + 0] = kv.x;
            Ks[row * ATT_LDP + c4 + 1] = kv.y;
            Ks[row * ATT_LDP + c4 + 2] = kv.z;
            Ks[row * ATT_LDP + c4 + 3] = kv.w;
            float4 vv = *(const float4*)(Vbase + (size_t)row * (HEADS * DK) + c4);
            Vs[row * ATT_LDP + c4 + 0] = vv.x;
            Vs[row * ATT_LDP + c4 + 1] = vv.y;
            Vs[row * ATT_LDP + c4 + 2] = vv.z;
            Vs[row * ATT_LDP + c4 + 3] = vv.w;
        }
        __syncthreads();

        float s[4][4];
#pragma unroll
        for (int i = 0; i < 4; i++)
#pragma unroll
            for (int j = 0; j < 4; j++) s[i][j] = 0.f;

#pragma unroll 4
        for (int d = 0; d < DK; d++) {
            float a[4], bb[4];
#pragma unroll
            for (int i = 0; i < 4; i++) a[i]  = Qs[(r0 + i) * ATT_LDP + d];
#pragma unroll
            for (int j = 0; j < 4; j++) bb[j] = Ks[(c0 + j) * ATT_LDP + d];
#pragma unroll
            for (int i = 0; i < 4; i++)
#pragma unroll
                for (int j = 0; j < 4; j++)
                    s[i][j] = fmaf(a[i], bb[j], s[i][j]);
        }

#pragma unroll
        for (int i = 0; i < 4; i++) {
            float mx = -INFINITY;
#pragma unroll
            for (int j = 0; j < 4; j++) {
                s[i][j] *= scale;
                mx = fmaxf(mx, s[i][j]);
            }
#pragma unroll
            for (int o = 8; o >= 1; o >>= 1)
                mx = fmaxf(mx, __shfl_xor_sync(0xffffffffu, mx, o));
            float m_new = fmaxf(m_i[i], mx);
            float corr = __expf(m_i[i] - m_new);
            float rs = 0.f;
#pragma unroll
            for (int j = 0; j < 4; j++) {
                s[i][j] = __expf(s[i][j] - m_new);
                rs += s[i][j];
            }
#pragma unroll
            for (int o = 8; o >= 1; o >>= 1)
                rs += __shfl_xor_sync(0xffffffffu, rs, o);
            l_i[i] = l_i[i] * corr + rs;
            m_i[i] = m_new;
#pragma unroll
            for (int j = 0; j < 4; j++) {
                O[i][j] *= corr;
                Ps[(r0 + i) * ATT_LDP + c0 + j] = s[i][j];
            }
        }
        __syncthreads();

#pragma unroll 4
        for (int k = 0; k < BKV; k++) {
            float p[4], v[4];
#pragma unroll
            for (int i = 0; i < 4; i++) p[i] = Ps[(r0 + i) * ATT_LDP + k];
#pragma unroll
            for (int j = 0; j < 4; j++) v[j] = Vs[k * ATT_LDP + c0 + j];
#pragma unroll
            for (int i = 0; i < 4; i++)
#pragma unroll
                for (int j = 0; j < 4; j++)
                    O[i][j] = fmaf(p[i], v[j], O[i][j]);
        }
    }

    float* Cbase = Cg + (((size_t)b * SEQ + (size_t)qt * BQ) * HEADS + h) * DK;
#pragma unroll
    for (int i = 0; i < 4; i++) {
        float inv_l = 1.f / l_i[i];
        float* cr = Cbase + (size_t)(r0 + i) * (HEADS * DK) + c0;
        float4 o;
        o.x = O[i][0] * inv_l; o.y = O[i][1] * inv_l;
        o.z = O[i][2] * inv_l; o.w = O[i][3] * inv_l;
        *(float4*)cr = o;
    }
}

// ===========================================================================
// Launch
// ===========================================================================
extern "C" void kernel_launch(void* const* d_in, const int* in_sizes, int n_in,
                              void* d_out, int out_size)
{
    const float* X  = (const float*)d_in[0];
    const float* Wq = (const float*)d_in[1];
    const float* bq = (const float*)d_in[2];
    const float* Wk = (const float*)d_in[3];
    const float* bk = (const float*)d_in[4];
    const float* Wv = (const float*)d_in[5];
    const float* bv = (const float*)d_in[6];
    const float* Wo = (const float*)d_in[7];
    const float* bo = (const float*)d_in[8];

    float *Qp, *Kp, *Vp, *Cp;
    cudaGetSymbolAddress((void**)&Qp, g_Q);
    cudaGetSymbolAddress((void**)&Kp, g_K);
    cudaGetSymbolAddress((void**)&Vp, g_V);
    cudaGetSymbolAddress((void**)&Cp, g_CTX);

    static bool attr_set = false;
    if (!attr_set) {
        cudaFuncSetAttribute(gemm_tc_kernel,
                             cudaFuncAttributeMaxDynamicSharedMemorySize, G_SMEM_BYTES);
        cudaFuncSetAttribute(attn_kernel,
                             cudaFuncAttributeMaxDynamicSharedMemorySize, ATT_SMEM_BYTES);
        attr_set = true;
    }

    dim3 ggrid(DIM / TBN, M_TOTAL / TBM);   // (8, 64)

    gemm_tc_kernel<<<ggrid, 256, G_SMEM_BYTES>>>(X, Wq, bq, Qp);
    gemm_tc_kernel<<<ggrid, 256, G_SMEM_BYTES>>>(X, Wk, bk, Kp);
    gemm_tc_kernel<<<ggrid, 256, G_SMEM_BYTES>>>(X, Wv, bv, Vp);

    attn_kernel<<<dim3(SEQ / BQ, HEADS, BATCH), 256, ATT_SMEM_BYTES>>>(Qp, Kp, Vp, Cp);

    gemm_tc_kernel<<<ggrid, 256, G_SMEM_BYTES>>>(Cp, Wo, bo, (float*)d_out);
}

// round 4
// speedup vs baseline: 3.1257x; 2.2274x over previous
#include <cuda_runtime.h>
#include <cstdint>
#include <math.h>

#define BATCH 4
#define SEQ 2048
#define DIM 1024
#define HEADS 16
#define DK 64
#define M_TOTAL (BATCH * SEQ)   // 8192

// Scratch buffers (device globals; no allocation allowed)
__device__ float g_Q[M_TOTAL * DIM];
__device__ float g_K[M_TOTAL * DIM];
__device__ float g_V[M_TOTAL * DIM];
__device__ float g_CTX[M_TOTAL * DIM];

// ===========================================================================
// Helpers
// ===========================================================================
__device__ __forceinline__ uint32_t f2tf32(float x) {
    uint32_t r;
    asm("cvt.rna.tf32.f32 %0, %1;" : "=r"(r) : "f"(x));
    return r;
}

__device__ __forceinline__ float f2tf32f(float x) {
    uint32_t r;
    asm("cvt.rna.tf32.f32 %0, %1;" : "=r"(r) : "f"(x));
    return __uint_as_float(r);
}

__device__ __forceinline__ void mma1688(float* d, const uint32_t* a, const uint32_t* b) {
    asm volatile(
        "mma.sync.aligned.m16n8k8.row.col.f32.tf32.tf32.f32 "
        "{%0,%1,%2,%3}, {%4,%5,%6,%7}, {%8,%9}, {%0,%1,%2,%3};"
        : "+f"(d[0]), "+f"(d[1]), "+f"(d[2]), "+f"(d[3])
        : "r"(a[0]), "r"(a[1]), "r"(a[2]), "r"(a[3]), "r"(b[0]), "r"(b[1]));
}

__device__ __forceinline__ uint32_t smem_addr_u32(const void* p) {
    uint32_t a;
    asm("{ .reg .u64 t; cvta.to.shared.u64 t, %1; cvt.u32.u64 %0, t; }" : "=r"(a) : "l"(p));
    return a;
}

// ===========================================================================
// tf32 tensor-core GEMM (unchanged from R3): Y = X @ W^T + bias
// ===========================================================================
#define TBM 128
#define TBN 128
#define TBK 32
#define LDS_ROW 36
#define MAT_FLOATS (TBM * LDS_ROW)
#define G_SMEM_BYTES (2 * 2 * MAT_FLOATS * 4)   // 73728

__global__ void __launch_bounds__(256, 2)
gemm_tc_kernel(const float* __restrict__ X, const float* __restrict__ W,
               const float* __restrict__ bias, float* __restrict__ Y)
{
    extern __shared__ float smem[];
    float* As = smem;
    float* Bs = smem + 2 * MAT_FLOATS;

    const int tid = threadIdx.x;
    const int wid = tid >> 5;
    const int lane = tid & 31;
    const int bm = blockIdx.y * TBM;
    const int bn = blockIdx.x * TBN;

    const int wm = (wid >> 2) * 64;
    const int wn = (wid & 3) * 32;

    const int lr = lane >> 2;
    const int lc = lane & 3;

    float acc[4][4][4];
#pragma unroll
    for (int i = 0; i < 4; i++)
#pragma unroll
        for (int j = 0; j < 4; j++)
#pragma unroll
            for (int r = 0; r < 4; r++) acc[i][j][r] = 0.f;

    auto issue_stage = [&](int kt, int buf) {
        const int k0 = kt * TBK;
        float* a_dst = As + buf * MAT_FLOATS;
        float* b_dst = Bs + buf * MAT_FLOATS;
#pragma unroll
        for (int l = 0; l < 4; l++) {
            int idx = tid + l * 256;
            int row = idx >> 3;
            int seg = (idx & 7) * 4;
            const float* src = X + (size_t)(bm + row) * DIM + k0 + seg;
            uint32_t dst = smem_addr_u32(a_dst + row * LDS_ROW + seg);
            asm volatile("cp.async.cg.shared.global [%0], [%1], 16;" :: "r"(dst), "l"(src));
        }
#pragma unroll
        for (int l = 0; l < 4; l++) {
            int idx = tid + l * 256;
            int row = idx >> 3;
            int seg = (idx & 7) * 4;
            const float* src = W + (size_t)(bn + row) * DIM + k0 + seg;
            uint32_t dst = smem_addr_u32(b_dst + row * LDS_ROW + seg);
            asm volatile("cp.async.cg.shared.global [%0], [%1], 16;" :: "r"(dst), "l"(src));
        }
        asm volatile("cp.async.commit_group;" ::: "memory");
    };

    const int n_kt = DIM / TBK;
    issue_stage(0, 0);

    for (int kt = 0; kt < n_kt; kt++) {
        if (kt + 1 < n_kt) {
            issue_stage(kt + 1, (kt + 1) & 1);
            asm volatile("cp.async.wait_group 1;" ::: "memory");
        } else {
            asm volatile("cp.async.wait_group 0;" ::: "memory");
        }
        __syncthreads();

        const float* a_s = As + (kt & 1) * MAT_FLOATS;
        const float* b_s = Bs + (kt & 1) * MAT_FLOATS;

#pragma unroll
        for (int ks = 0; ks < 4; ks++) {
            const int k = ks * 8 + lc;
            uint32_t af[4][4];
#pragma unroll
            for (int mt = 0; mt < 4; mt++) {
                const float* p = a_s + (wm + mt * 16 + lr) * LDS_ROW + k;
                af[mt][0] = f2tf32(p[0]);
                af[mt][1] = f2tf32(p[8 * LDS_ROW]);
                af[mt][2] = f2tf32(p[4]);
                af[mt][3] = f2tf32(p[8 * LDS_ROW + 4]);
            }
            uint32_t bf[4][2];
#pragma unroll
            for (int nt = 0; nt < 4; nt++) {
                const float* p = b_s + (wn + nt * 8 + lr) * LDS_ROW + k;
                bf[nt][0] = f2tf32(p[0]);
                bf[nt][1] = f2tf32(p[4]);
            }
#pragma unroll
            for (int mt = 0; mt < 4; mt++)
#pragma unroll
                for (int nt = 0; nt < 4; nt++)
                    mma1688(acc[mt][nt], af[mt], bf[nt]);
        }
        __syncthreads();
    }

#pragma unroll
    for (int mt = 0; mt < 4; mt++) {
#pragma unroll
        for (int nt = 0; nt < 4; nt++) {
            const int row = bm + wm + mt * 16 + lr;
            const int col = bn + wn + nt * 8 + lc * 2;
            float2 bv = *(const float2*)(bias + col);
            float2 o0, o1;
            o0.x = acc[mt][nt][0] + bv.x;
            o0.y = acc[mt][nt][1] + bv.y;
            o1.x = acc[mt][nt][2] + bv.x;
            o1.y = acc[mt][nt][3] + bv.y;
            *(float2*)(Y + (size_t)row * DIM + col)       = o0;
            *(float2*)(Y + (size_t)(row + 8) * DIM + col) = o1;
        }
    }
}

// ===========================================================================
// Tensor-core flash attention (tf32 mma.sync).
// Grid: (SEQ/128, HEADS, BATCH). 256 threads = 8 warps, 16 query rows/warp.
// KV tiles of 64 rows, double-buffered cp.async, rna-rounded in place.
// Smem rows padded to 72 floats -> conflict-free fragment gathers.
// ===========================================================================
#define ABQ 128
#define ABKV 64
#define ALD 72
#define KV_TILE_FLOATS (ABKV * ALD)     // 4608
#define QP_FLOATS (ABQ * ALD)           // 9216
#define ATT_SMEM_BYTES ((4 * KV_TILE_FLOATS + QP_FLOATS) * 4)   // 110592

__global__ void __launch_bounds__(256, 1)
attn_tc_kernel(const float* __restrict__ Qg, const float* __restrict__ Kg,
               const float* __restrict__ Vg, float* __restrict__ Cg)
{
    extern __shared__ float smem[];
    float* Kb = smem;                       // [2][64][72]
    float* Vb = smem + 2 * KV_TILE_FLOATS;  // [2][64][72]
    float* QP = smem + 4 * KV_TILE_FLOATS;  // Q tile [128][72], later P scratch

    const int qt = blockIdx.x;
    const int h  = blockIdx.y;
    const int b  = blockIdx.z;
    const int tid = threadIdx.x;
    const int wid = tid >> 5;
    const int lane = tid & 31;
    const int lr = lane >> 2;
    const int lc = lane & 3;
    const int q0 = wid * 16;
    const size_t RS = HEADS * DK;   // 1024 gmem row stride

    const float* Qbase = Qg + ((size_t)(b * SEQ + qt * ABQ) * HEADS + h) * DK;
    const float* Kh = Kg + ((size_t)b * SEQ * HEADS + h) * DK;
    const float* Vh = Vg + ((size_t)b * SEQ * HEADS + h) * DK;

    // ---- group A: load Q tile (128 x 64) ----
#pragma unroll
    for (int l = 0; l < 8; l++) {
        int idx = tid + l * 256;
        int row = idx >> 4;
        int seg = (idx & 15) * 4;
        const float* src = Qbase + (size_t)row * RS + seg;
        uint32_t dst = smem_addr_u32(QP + row * ALD + seg);
        asm volatile("cp.async.cg.shared.global [%0], [%1], 16;" :: "r"(dst), "l"(src));
    }
    asm volatile("cp.async.commit_group;" ::: "memory");

    auto issue_kv = [&](int t, int buf) {
        const size_t s0 = (size_t)t * ABKV;
        float* kd = Kb + buf * KV_TILE_FLOATS;
        float* vd = Vb + buf * KV_TILE_FLOATS;
#pragma unroll
        for (int l = 0; l < 4; l++) {
            int idx = tid + l * 256;
            int row = idx >> 4;
            int seg = (idx & 15) * 4;
            const float* src = Kh + (s0 + row) * RS + seg;
            uint32_t dst = smem_addr_u32(kd + row * ALD + seg);
            asm volatile("cp.async.cg.shared.global [%0], [%1], 16;" :: "r"(dst), "l"(src));
        }
#pragma unroll
        for (int l = 0; l < 4; l++) {
            int idx = tid + l * 256;
            int row = idx >> 4;
            int seg = (idx & 15) * 4;
            const float* src = Vh + (s0 + row) * RS + seg;
            uint32_t dst = smem_addr_u32(vd + row * ALD + seg);
            asm volatile("cp.async.cg.shared.global [%0], [%1], 16;" :: "r"(dst), "l"(src));
        }
        asm volatile("cp.async.commit_group;" ::: "memory");
    };

    issue_kv(0, 0);                                   // group B
    asm volatile("cp.async.wait_group 1;" ::: "memory");  // Q (A) done
    __syncthreads();

    // ---- build Q fragments (scale 1/8 folded in; rna -> tf32) ----
    uint32_t aq[8][4];
#pragma unroll
    for (int kk = 0; kk < 8; kk++) {
        const float* p = QP + (q0 + lr) * ALD + kk * 8 + lc;
        aq[kk][0] = f2tf32(0.125f * p[0]);
        aq[kk][1] = f2tf32(0.125f * p[8 * ALD]);
        aq[kk][2] = f2tf32(0.125f * p[4]);
        aq[kk][3] = f2tf32(0.125f * p[8 * ALD + 4]);
    }
    // QP now becomes per-warp P scratch (each warp reuses its own 16 rows)
    float* Pw = QP + q0 * ALD;

    float oacc[8][4];
    float m_i[2] = {-INFINITY, -INFINITY};
    float l_i[2] = {0.f, 0.f};
#pragma unroll
    for (int nt = 0; nt < 8; nt++)
#pragma unroll
        for (int r = 0; r < 4; r++) oacc[nt][r] = 0.f;

    const int n_t = SEQ / ABKV;   // 32
    for (int t = 0; t < n_t; t++) {
        if (t + 1 < n_t) {
            issue_kv(t + 1, (t + 1) & 1);
            asm volatile("cp.async.wait_group 1;" ::: "memory");
        } else {
            asm volatile("cp.async.wait_group 0;" ::: "memory");
        }
        __syncthreads();

        float* ks = Kb + (t & 1) * KV_TILE_FLOATS;
        float* vs = Vb + (t & 1) * KV_TILE_FLOATS;

        // in-place rna rounding of K and V tiles (64x64 data region)
#pragma unroll
        for (int l = 0; l < 4; l++) {
            int idx = tid + l * 256;
            int row = idx >> 4;
            int seg = (idx & 15) * 4;
            float4* kp = (float4*)(ks + row * ALD + seg);
            float4 kv = *kp;
            kv.x = f2tf32f(kv.x); kv.y = f2tf32f(kv.y);
            kv.z = f2tf32f(kv.z); kv.w = f2tf32f(kv.w);
            *kp = kv;
            float4* vp = (float4*)(vs + row * ALD + seg);
            float4 vv = *vp;
            vv.x = f2tf32f(vv.x); vv.y = f2tf32f(vv.y);
            vv.z = f2tf32f(vv.z); vv.w = f2tf32f(vv.w);
            *vp = vv;
        }
        __syncthreads();

        // ---- S = (Q*scale) @ K^T  (16 x 64 per warp) ----
        float sacc[8][4];
#pragma unroll
        for (int nt = 0; nt < 8; nt++)
#pragma unroll
            for (int r = 0; r < 4; r++) sacc[nt][r] = 0.f;

#pragma unroll
        for (int kk = 0; kk < 8; kk++) {
            uint32_t bk[8][2];
#pragma unroll
            for (int nt = 0; nt < 8; nt++) {
                const float* p = ks + (nt * 8 + lr) * ALD + kk * 8 + lc;
                bk[nt][0] = __float_as_uint(p[0]);
                bk[nt][1] = __float_as_uint(p[4]);
            }
#pragma unroll
            for (int nt = 0; nt < 8; nt++)
                mma1688(sacc[nt], aq[kk], bk[nt]);
        }

        // ---- online softmax (2 rows per thread: lr, lr+8) ----
#pragma unroll
        for (int j = 0; j < 2; j++) {
            float mx = -INFINITY;
#pragma unroll
            for (int nt = 0; nt < 8; nt++) {
                mx = fmaxf(mx, sacc[nt][2 * j]);
                mx = fmaxf(mx, sacc[nt][2 * j + 1]);
            }
            mx = fmaxf(mx, __shfl_xor_sync(0xffffffffu, mx, 1));
            mx = fmaxf(mx, __shfl_xor_sync(0xffffffffu, mx, 2));
            float m_new = fmaxf(m_i[j], mx);
            float corr = __expf(m_i[j] - m_new);
            float rs = 0.f;
#pragma unroll
            for (int nt = 0; nt < 8; nt++) {
                float p0 = __expf(sacc[nt][2 * j]     - m_new);
                float p1 = __expf(sacc[nt][2 * j + 1] - m_new);
                sacc[nt][2 * j]     = p0;
                sacc[nt][2 * j + 1] = p1;
                rs += p0 + p1;
            }
            rs += __shfl_xor_sync(0xffffffffu, rs, 1);
            rs += __shfl_xor_sync(0xffffffffu, rs, 2);
            l_i[j] = l_i[j] * corr + rs;
            m_i[j] = m_new;
#pragma unroll
            for (int nt = 0; nt < 8; nt++) {
                oacc[nt][2 * j]     *= corr;
                oacc[nt][2 * j + 1] *= corr;
            }
        }

        // ---- store P (rna-rounded) to warp-private smem ----
#pragma unroll
        for (int nt = 0; nt < 8; nt++) {
            float2 p01, p23;
            p01.x = f2tf32f(sacc[nt][0]); p01.y = f2tf32f(sacc[nt][1]);
            p23.x = f2tf32f(sacc[nt][2]); p23.y = f2tf32f(sacc[nt][3]);
            *(float2*)(Pw + lr * ALD + nt * 8 + 2 * lc)       = p01;
            *(float2*)(Pw + (lr + 8) * ALD + nt * 8 + 2 * lc) = p23;
        }
        __syncwarp();

        // ---- O += P @ V  (k over kv, n over dk) ----
#pragma unroll
        for (int kk = 0; kk < 8; kk++) {
            uint32_t ap[4];
            const float* pp = Pw + lr * ALD + kk * 8 + lc;
            ap[0] = __float_as_uint(pp[0]);
            ap[1] = __float_as_uint(pp[8 * ALD]);
            ap[2] = __float_as_uint(pp[4]);
            ap[3] = __float_as_uint(pp[8 * ALD + 4]);
#pragma unroll
            for (int nt = 0; nt < 8; nt++) {
                const float* vp = vs + (kk * 8 + lc) * ALD + nt * 8 + lr;
                uint32_t bv[2];
                bv[0] = __float_as_uint(vp[0]);
                bv[1] = __float_as_uint(vp[4 * ALD]);
                mma1688(oacc[nt], ap, bv);
            }
        }
        __syncthreads();
    }

    // ---- epilogue: normalize, write ctx ----
    float* Cbase = Cg + ((size_t)(b * SEQ + qt * ABQ) * HEADS + h) * DK;
    const float inv0 = 1.f / l_i[0];
    const float inv1 = 1.f / l_i[1];
    const int r0g = q0 + lr;
    const int r1g = q0 + lr + 8;
#pragma unroll
    for (int nt = 0; nt < 8; nt++) {
        const int col = nt * 8 + 2 * lc;
        float2 o0, o1;
        o0.x = oacc[nt][0] * inv0; o0.y = oacc[nt][1] * inv0;
        o1.x = oacc[nt][2] * inv1; o1.y = oacc[nt][3] * inv1;
        *(float2*)(Cbase + (size_t)r0g * RS + col) = o0;
        *(float2*)(Cbase + (size_t)r1g * RS + col) = o1;
    }
}

// ===========================================================================
// Launch
// ===========================================================================
extern "C" void kernel_launch(void* const* d_in, const int* in_sizes, int n_in,
                              void* d_out, int out_size)
{
    const float* X  = (const float*)d_in[0];
    const float* Wq = (const float*)d_in[1];
    const float* bq = (const float*)d_in[2];
    const float* Wk = (const float*)d_in[3];
    const float* bk = (const float*)d_in[4];
    const float* Wv = (const float*)d_in[5];
    const float* bv = (const float*)d_in[6];
    const float* Wo = (const float*)d_in[7];
    const float* bo = (const float*)d_in[8];

    float *Qp, *Kp, *Vp, *Cp;
    cudaGetSymbolAddress((void**)&Qp, g_Q);
    cudaGetSymbolAddress((void**)&Kp, g_K);
    cudaGetSymbolAddress((void**)&Vp, g_V);
    cudaGetSymbolAddress((void**)&Cp, g_CTX);

    static bool attr_set = false;
    if (!attr_set) {
        cudaFuncSetAttribute(gemm_tc_kernel,
                             cudaFuncAttributeMaxDynamicSharedMemorySize, G_SMEM_BYTES);
        cudaFuncSetAttribute(attn_tc_kernel,
                             cudaFuncAttributeMaxDynamicSharedMemorySize, ATT_SMEM_BYTES);
        attr_set = true;
    }

    dim3 ggrid(DIM / TBN, M_TOTAL / TBM);   // (8, 64)

    gemm_tc_kernel<<<ggrid, 256, G_SMEM_BYTES>>>(X, Wq, bq, Qp);
    gemm_tc_kernel<<<ggrid, 256, G_SMEM_BYTES>>>(X, Wk, bk, Kp);
    gemm_tc_kernel<<<ggrid, 256, G_SMEM_BYTES>>>(X, Wv, bv, Vp);

    attn_tc_kernel<<<dim3(SEQ / ABQ, HEADS, BATCH), 256, ATT_SMEM_BYTES>>>(Qp, Kp, Vp, Cp);

    gemm_tc_kernel<<<ggrid, 256, G_SMEM_BYTES>>>(Cp, Wo, bo, (float*)d_out);
}

// round 5
// speedup vs baseline: 3.7660x; 1.2049x over previous
#include <cuda_runtime.h>
#include <cstdint>
#include <math.h>

#define BATCH 4
#define SEQ 2048
#define DIM 1024
#define HEADS 16
#define DK 64
#define M_TOTAL (BATCH * SEQ)   // 8192

// Scratch buffers (device globals; no allocation allowed)
__device__ float g_Q[M_TOTAL * DIM];
__device__ float g_K[M_TOTAL * DIM];
__device__ float g_V[M_TOTAL * DIM];
__device__ float g_CTX[M_TOTAL * DIM];

// ===========================================================================
// Helpers
// ===========================================================================
__device__ __forceinline__ uint32_t f2tf32(float x) {
    uint32_t r;
    asm("cvt.rna.tf32.f32 %0, %1;" : "=r"(r) : "f"(x));
    return r;
}

__device__ __forceinline__ float f2tf32f(float x) {
    uint32_t r;
    asm("cvt.rna.tf32.f32 %0, %1;" : "=r"(r) : "f"(x));
    return __uint_as_float(r);
}

__device__ __forceinline__ void mma1688(float* d, const uint32_t* a, const uint32_t* b) {
    asm volatile(
        "mma.sync.aligned.m16n8k8.row.col.f32.tf32.tf32.f32 "
        "{%0,%1,%2,%3}, {%4,%5,%6,%7}, {%8,%9}, {%0,%1,%2,%3};"
        : "+f"(d[0]), "+f"(d[1]), "+f"(d[2]), "+f"(d[3])
        : "r"(a[0]), "r"(a[1]), "r"(a[2]), "r"(a[3]), "r"(b[0]), "r"(b[1]));
}

__device__ __forceinline__ uint32_t smem_addr_u32(const void* p) {
    uint32_t a;
    asm("{ .reg .u64 t; cvta.to.shared.u64 t, %1; cvt.u32.u64 %0, t; }" : "=r"(a) : "l"(p));
    return a;
}

// ===========================================================================
// tf32 tensor-core GEMM body: Y = X @ W^T + bias, optional tf32-round of output
// Tile 128x128, BK=32, double-buffered cp.async. 256 threads / 8 warps.
// ===========================================================================
#define TBM 128
#define TBN 128
#define TBK 32
#define LDS_ROW 36
#define MAT_FLOATS (TBM * LDS_ROW)
#define G_SMEM_BYTES (2 * 2 * MAT_FLOATS * 4)   // 73728

template <bool ROUND_OUT>
__device__ __forceinline__ void gemm_body(
    float* smem,
    const float* __restrict__ X, const float* __restrict__ W,
    const float* __restrict__ bias, float* __restrict__ Y,
    int bm, int bn)
{
    float* As = smem;
    float* Bs = smem + 2 * MAT_FLOATS;

    const int tid = threadIdx.x;
    const int wid = tid >> 5;
    const int lane = tid & 31;
    const int wm = (wid >> 2) * 64;
    const int wn = (wid & 3) * 32;
    const int lr = lane >> 2;
    const int lc = lane & 3;

    float acc[4][4][4];
#pragma unroll
    for (int i = 0; i < 4; i++)
#pragma unroll
        for (int j = 0; j < 4; j++)
#pragma unroll
            for (int r = 0; r < 4; r++) acc[i][j][r] = 0.f;

    auto issue_stage = [&](int kt, int buf) {
        const int k0 = kt * TBK;
        float* a_dst = As + buf * MAT_FLOATS;
        float* b_dst = Bs + buf * MAT_FLOATS;
#pragma unroll
        for (int l = 0; l < 4; l++) {
            int idx = tid + l * 256;
            int row = idx >> 3;
            int seg = (idx & 7) * 4;
            const float* src = X + (size_t)(bm + row) * DIM + k0 + seg;
            uint32_t dst = smem_addr_u32(a_dst + row * LDS_ROW + seg);
            asm volatile("cp.async.cg.shared.global [%0], [%1], 16;" :: "r"(dst), "l"(src));
        }
#pragma unroll
        for (int l = 0; l < 4; l++) {
            int idx = tid + l * 256;
            int row = idx >> 3;
            int seg = (idx & 7) * 4;
            const float* src = W + (size_t)(bn + row) * DIM + k0 + seg;
            uint32_t dst = smem_addr_u32(b_dst + row * LDS_ROW + seg);
            asm volatile("cp.async.cg.shared.global [%0], [%1], 16;" :: "r"(dst), "l"(src));
        }
        asm volatile("cp.async.commit_group;" ::: "memory");
    };

    const int n_kt = DIM / TBK;
    issue_stage(0, 0);

    for (int kt = 0; kt < n_kt; kt++) {
        if (kt + 1 < n_kt) {
            issue_stage(kt + 1, (kt + 1) & 1);
            asm volatile("cp.async.wait_group 1;" ::: "memory");
        } else {
            asm volatile("cp.async.wait_group 0;" ::: "memory");
        }
        __syncthreads();

        const float* a_s = As + (kt & 1) * MAT_FLOATS;
        const float* b_s = Bs + (kt & 1) * MAT_FLOATS;

#pragma unroll
        for (int ks = 0; ks < 4; ks++) {
            const int k = ks * 8 + lc;
            uint32_t af[4][4];
#pragma unroll
            for (int mt = 0; mt < 4; mt++) {
                const float* p = a_s + (wm + mt * 16 + lr) * LDS_ROW + k;
                af[mt][0] = f2tf32(p[0]);
                af[mt][1] = f2tf32(p[8 * LDS_ROW]);
                af[mt][2] = f2tf32(p[4]);
                af[mt][3] = f2tf32(p[8 * LDS_ROW + 4]);
            }
            uint32_t bf[4][2];
#pragma unroll
            for (int nt = 0; nt < 4; nt++) {
                const float* p = b_s + (wn + nt * 8 + lr) * LDS_ROW + k;
                bf[nt][0] = f2tf32(p[0]);
                bf[nt][1] = f2tf32(p[4]);
            }
#pragma unroll
            for (int mt = 0; mt < 4; mt++)
#pragma unroll
                for (int nt = 0; nt < 4; nt++)
                    mma1688(acc[mt][nt], af[mt], bf[nt]);
        }
        __syncthreads();
    }

#pragma unroll
    for (int mt = 0; mt < 4; mt++) {
#pragma unroll
        for (int nt = 0; nt < 4; nt++) {
            const int row = bm + wm + mt * 16 + lr;
            const int col = bn + wn + nt * 8 + lc * 2;
            float2 bv = *(const float2*)(bias + col);
            float2 o0, o1;
            if (ROUND_OUT) {
                o0.x = f2tf32f(acc[mt][nt][0] + bv.x);
                o0.y = f2tf32f(acc[mt][nt][1] + bv.y);
                o1.x = f2tf32f(acc[mt][nt][2] + bv.x);
                o1.y = f2tf32f(acc[mt][nt][3] + bv.y);
            } else {
                o0.x = acc[mt][nt][0] + bv.x;
                o0.y = acc[mt][nt][1] + bv.y;
                o1.x = acc[mt][nt][2] + bv.x;
                o1.y = acc[mt][nt][3] + bv.y;
            }
            *(float2*)(Y + (size_t)row * DIM + col)       = o0;
            *(float2*)(Y + (size_t)(row + 8) * DIM + col) = o1;
        }
    }
}

// Fused Q/K/V projection: blockIdx.z selects weight/bias/output. Output tf32-rounded.
__global__ void __launch_bounds__(256, 2)
gemm_qkv_kernel(const float* __restrict__ X,
                const float* __restrict__ Wq, const float* __restrict__ bq, float* __restrict__ Qo,
                const float* __restrict__ Wk, const float* __restrict__ bk, float* __restrict__ Ko,
                const float* __restrict__ Wv, const float* __restrict__ bv, float* __restrict__ Vo)
{
    extern __shared__ float smem[];
    const int z = blockIdx.z;
    const float* W = (z == 0) ? Wq : (z == 1) ? Wk : Wv;
    const float* b = (z == 0) ? bq : (z == 1) ? bk : bv;
    float* Y       = (z == 0) ? Qo : (z == 1) ? Ko : Vo;
    gemm_body<true>(smem, X, W, b, Y, blockIdx.y * TBM, blockIdx.x * TBN);
}

// Output projection: no rounding of result.
__global__ void __launch_bounds__(256, 2)
gemm_o_kernel(const float* __restrict__ X, const float* __restrict__ W,
              const float* __restrict__ bias, float* __restrict__ Y)
{
    extern __shared__ float smem[];
    gemm_body<false>(smem, X, W, bias, Y, blockIdx.y * TBM, blockIdx.x * TBN);
}

// ===========================================================================
// Tensor-core flash attention (tf32 mma.sync).
// Grid: (SEQ/128, HEADS, BATCH). 256 threads = 8 warps, 16 query rows/warp.
// Inputs Q/K/V are pre-rounded to tf32 by the projection GEMM epilogue.
// Scores scaled AFTER QK^T by 1/8 (exact). 2 CTAs/SM via launch_bounds.
// ===========================================================================
#define ABQ 128
#define ABKV 64
#define ALD 72
#define KV_TILE_FLOATS (ABKV * ALD)     // 4608
#define QP_FLOATS (ABQ * ALD)           // 9216
#define ATT_SMEM_BYTES ((4 * KV_TILE_FLOATS + QP_FLOATS) * 4)   // 110592

__global__ void __launch_bounds__(256, 2)
attn_tc_kernel(const float* __restrict__ Qg, const float* __restrict__ Kg,
               const float* __restrict__ Vg, float* __restrict__ Cg)
{
    extern __shared__ float smem[];
    float* Kb = smem;                       // [2][64][72]
    float* Vb = smem + 2 * KV_TILE_FLOATS;  // [2][64][72]
    float* QP = smem + 4 * KV_TILE_FLOATS;  // Q tile [128][72], later P scratch

    const int qt = blockIdx.x;
    const int h  = blockIdx.y;
    const int b  = blockIdx.z;
    const int tid = threadIdx.x;
    const int wid = tid >> 5;
    const int lane = tid & 31;
    const int lr = lane >> 2;
    const int lc = lane & 3;
    const int q0 = wid * 16;
    const size_t RS = HEADS * DK;   // 1024 gmem row stride

    const float* Qbase = Qg + ((size_t)(b * SEQ + qt * ABQ) * HEADS + h) * DK;
    const float* Kh = Kg + ((size_t)b * SEQ * HEADS + h) * DK;
    const float* Vh = Vg + ((size_t)b * SEQ * HEADS + h) * DK;

    // ---- group A: load Q tile (128 x 64) ----
#pragma unroll
    for (int l = 0; l < 8; l++) {
        int idx = tid + l * 256;
        int row = idx >> 4;
        int seg = (idx & 15) * 4;
        const float* src = Qbase + (size_t)row * RS + seg;
        uint32_t dst = smem_addr_u32(QP + row * ALD + seg);
        asm volatile("cp.async.cg.shared.global [%0], [%1], 16;" :: "r"(dst), "l"(src));
    }
    asm volatile("cp.async.commit_group;" ::: "memory");

    auto issue_kv = [&](int t, int buf) {
        const size_t s0 = (size_t)t * ABKV;
        float* kd = Kb + buf * KV_TILE_FLOATS;
        float* vd = Vb + buf * KV_TILE_FLOATS;
#pragma unroll
        for (int l = 0; l < 4; l++) {
            int idx = tid + l * 256;
            int row = idx >> 4;
            int seg = (idx & 15) * 4;
            const float* src = Kh + (s0 + row) * RS + seg;
            uint32_t dst = smem_addr_u32(kd + row * ALD + seg);
            asm volatile("cp.async.cg.shared.global [%0], [%1], 16;" :: "r"(dst), "l"(src));
        }
#pragma unroll
        for (int l = 0; l < 4; l++) {
            int idx = tid + l * 256;
            int row = idx >> 4;
            int seg = (idx & 15) * 4;
            const float* src = Vh + (s0 + row) * RS + seg;
            uint32_t dst = smem_addr_u32(vd + row * ALD + seg);
            asm volatile("cp.async.cg.shared.global [%0], [%1], 16;" :: "r"(dst), "l"(src));
        }
        asm volatile("cp.async.commit_group;" ::: "memory");
    };

    issue_kv(0, 0);                                       // group B
    asm volatile("cp.async.wait_group 1;" ::: "memory");  // Q (A) done
    __syncthreads();

    // ---- build Q fragments (pre-rounded tf32 bit patterns; no scaling) ----
    uint32_t aq[8][4];
#pragma unroll
    for (int kk = 0; kk < 8; kk++) {
        const float* p = QP + (q0 + lr) * ALD + kk * 8 + lc;
        aq[kk][0] = __float_as_uint(p[0]);
        aq[kk][1] = __float_as_uint(p[8 * ALD]);
        aq[kk][2] = __float_as_uint(p[4]);
        aq[kk][3] = __float_as_uint(p[8 * ALD + 4]);
    }
    __syncthreads();
    // QP now becomes per-warp P scratch (each warp reuses its own 16 rows)
    float* Pw = QP + q0 * ALD;

    float oacc[8][4];
    float m_i[2] = {-INFINITY, -INFINITY};
    float l_i[2] = {0.f, 0.f};
#pragma unroll
    for (int nt = 0; nt < 8; nt++)
#pragma unroll
        for (int r = 0; r < 4; r++) oacc[nt][r] = 0.f;

    const int n_t = SEQ / ABKV;   // 32
    for (int t = 0; t < n_t; t++) {
        if (t + 1 < n_t) {
            issue_kv(t + 1, (t + 1) & 1);
            asm volatile("cp.async.wait_group 1;" ::: "memory");
        } else {
            asm volatile("cp.async.wait_group 0;" ::: "memory");
        }
        __syncthreads();

        const float* ks = Kb + (t & 1) * KV_TILE_FLOATS;
        const float* vs = Vb + (t & 1) * KV_TILE_FLOATS;

        // ---- S = Q @ K^T  (16 x 64 per warp) ----
        float sacc[8][4];
#pragma unroll
        for (int nt = 0; nt < 8; nt++)
#pragma unroll
            for (int r = 0; r < 4; r++) sacc[nt][r] = 0.f;

#pragma unroll
        for (int kk = 0; kk < 8; kk++) {
#pragma unroll
            for (int nt = 0; nt < 8; nt++) {
                const float* p = ks + (nt * 8 + lr) * ALD + kk * 8 + lc;
                uint32_t bk[2];
                bk[0] = __float_as_uint(p[0]);
                bk[1] = __float_as_uint(p[4]);
                mma1688(sacc[nt], aq[kk], bk);
            }
        }

        // ---- online softmax (scale applied post-mma; rows lr, lr+8) ----
#pragma unroll
        for (int j = 0; j < 2; j++) {
            float mx = -INFINITY;
#pragma unroll
            for (int nt = 0; nt < 8; nt++) {
                sacc[nt][2 * j]     *= 0.125f;
                sacc[nt][2 * j + 1] *= 0.125f;
                mx = fmaxf(mx, sacc[nt][2 * j]);
                mx = fmaxf(mx, sacc[nt][2 * j + 1]);
            }
            mx = fmaxf(mx, __shfl_xor_sync(0xffffffffu, mx, 1));
            mx = fmaxf(mx, __shfl_xor_sync(0xffffffffu, mx, 2));
            float m_new = fmaxf(m_i[j], mx);
            float corr = __expf(m_i[j] - m_new);
            float rs = 0.f;
#pragma unroll
            for (int nt = 0; nt < 8; nt++) {
                float p0 = __expf(sacc[nt][2 * j]     - m_new);
                float p1 = __expf(sacc[nt][2 * j + 1] - m_new);
                sacc[nt][2 * j]     = p0;
                sacc[nt][2 * j + 1] = p1;
                rs += p0 + p1;
            }
            rs += __shfl_xor_sync(0xffffffffu, rs, 1);
            rs += __shfl_xor_sync(0xffffffffu, rs, 2);
            l_i[j] = l_i[j] * corr + rs;
            m_i[j] = m_new;
#pragma unroll
            for (int nt = 0; nt < 8; nt++) {
                oacc[nt][2 * j]     *= corr;
                oacc[nt][2 * j + 1] *= corr;
            }
        }

        // ---- store P (rna-rounded) to warp-private smem ----
#pragma unroll
        for (int nt = 0; nt < 8; nt++) {
            float2 p01, p23;
            p01.x = f2tf32f(sacc[nt][0]); p01.y = f2tf32f(sacc[nt][1]);
            p23.x = f2tf32f(sacc[nt][2]); p23.y = f2tf32f(sacc[nt][3]);
            *(float2*)(Pw + lr * ALD + nt * 8 + 2 * lc)       = p01;
            *(float2*)(Pw + (lr + 8) * ALD + nt * 8 + 2 * lc) = p23;
        }
        __syncwarp();

        // ---- O += P @ V  (k over kv, n over dk) ----
#pragma unroll
        for (int kk = 0; kk < 8; kk++) {
            uint32_t ap[4];
            const float* pp = Pw + lr * ALD + kk * 8 + lc;
            ap[0] = __float_as_uint(pp[0]);
            ap[1] = __float_as_uint(pp[8 * ALD]);
            ap[2] = __float_as_uint(pp[4]);
            ap[3] = __float_as_uint(pp[8 * ALD + 4]);
#pragma unroll
            for (int nt = 0; nt < 8; nt++) {
                const float* vp = vs + (kk * 8 + lc) * ALD + nt * 8 + lr;
                uint32_t bv[2];
                bv[0] = __float_as_uint(vp[0]);
                bv[1] = __float_as_uint(vp[4 * ALD]);
                mma1688(oacc[nt], ap, bv);
            }
        }
        __syncthreads();
    }

    // ---- epilogue: normalize, write ctx ----
    float* Cbase = Cg + ((size_t)(b * SEQ + qt * ABQ) * HEADS + h) * DK;
    const float inv0 = 1.f / l_i[0];
    const float inv1 = 1.f / l_i[1];
    const int r0g = q0 + lr;
    const int r1g = q0 + lr + 8;
#pragma unroll
    for (int nt = 0; nt < 8; nt++) {
        const int col = nt * 8 + 2 * lc;
        float2 o0, o1;
        o0.x = oacc[nt][0] * inv0; o0.y = oacc[nt][1] * inv0;
        o1.x = oacc[nt][2] * inv1; o1.y = oacc[nt][3] * inv1;
        *(float2*)(Cbase + (size_t)r0g * RS + col) = o0;
        *(float2*)(Cbase + (size_t)r1g * RS + col) = o1;
    }
}

// ===========================================================================
// Launch
// ===========================================================================
extern "C" void kernel_launch(void* const* d_in, const int* in_sizes, int n_in,
                              void* d_out, int out_size)
{
    const float* X  = (const float*)d_in[0];
    const float* Wq = (const float*)d_in[1];
    const float* bq = (const float*)d_in[2];
    const float* Wk = (const float*)d_in[3];
    const float* bk = (const float*)d_in[4];
    const float* Wv = (const float*)d_in[5];
    const float* bv = (const float*)d_in[6];
    const float* Wo = (const float*)d_in[7];
    const float* bo = (const float*)d_in[8];

    float *Qp, *Kp, *Vp, *Cp;
    cudaGetSymbolAddress((void**)&Qp, g_Q);
    cudaGetSymbolAddress((void**)&Kp, g_K);
    cudaGetSymbolAddress((void**)&Vp, g_V);
    cudaGetSymbolAddress((void**)&Cp, g_CTX);

    static bool attr_set = false;
    if (!attr_set) {
        cudaFuncSetAttribute(gemm_qkv_kernel,
                             cudaFuncAttributeMaxDynamicSharedMemorySize, G_SMEM_BYTES);
        cudaFuncSetAttribute(gemm_o_kernel,
                             cudaFuncAttributeMaxDynamicSharedMemorySize, G_SMEM_BYTES);
        cudaFuncSetAttribute(attn_tc_kernel,
                             cudaFuncAttributeMaxDynamicSharedMemorySize, ATT_SMEM_BYTES);
        attr_set = true;
    }

    dim3 qkv_grid(DIM / TBN, M_TOTAL / TBM, 3);   // (8, 64, 3)
    gemm_qkv_kernel<<<qkv_grid, 256, G_SMEM_BYTES>>>(X, Wq, bq, Qp,
                                                     Wk, bk, Kp,
                                                     Wv, bv, Vp);

    attn_tc_kernel<<<dim3(SEQ / ABQ, HEADS, BATCH), 256, ATT_SMEM_BYTES>>>(Qp, Kp, Vp, Cp);

    dim3 o_grid(DIM / TBN, M_TOTAL / TBM);        // (8, 64)
    gemm_o_kernel<<<o_grid, 256, G_SMEM_BYTES>>>(Cp, Wo, bo, (float*)d_out);
}

// round 6
// speedup vs baseline: 3.7702x; 1.0011x over previous
#include <cuda_runtime.h>
#include <cstdint>
#include <math.h>

#define BATCH 4
#define SEQ 2048
#define DIM 1024
#define HEADS 16
#define DK 64
#define M_TOTAL (BATCH * SEQ)   // 8192

// Scratch buffers (device globals; no allocation allowed)
__device__ float g_Q[M_TOTAL * DIM];
__device__ float g_K[M_TOTAL * DIM];
__device__ float g_V[M_TOTAL * DIM];
__device__ float g_CTX[M_TOTAL * DIM];
__device__ float g_Xr[M_TOTAL * DIM];    // tf32-rounded activations
__device__ float g_Wqr[DIM * DIM];
__device__ float g_Wkr[DIM * DIM];
__device__ float g_Wvr[DIM * DIM];
__device__ float g_Wor[DIM * DIM];

// ===========================================================================
// Helpers
// ===========================================================================
__device__ __forceinline__ float f2tf32f(float x) {
    uint32_t r;
    asm("cvt.rna.tf32.f32 %0, %1;" : "=r"(r) : "f"(x));
    return __uint_as_float(r);
}

__device__ __forceinline__ void mma1688(float* d, const uint32_t* a, const uint32_t* b) {
    asm volatile(
        "mma.sync.aligned.m16n8k8.row.col.f32.tf32.tf32.f32 "
        "{%0,%1,%2,%3}, {%4,%5,%6,%7}, {%8,%9}, {%0,%1,%2,%3};"
        : "+f"(d[0]), "+f"(d[1]), "+f"(d[2]), "+f"(d[3])
        : "r"(a[0]), "r"(a[1]), "r"(a[2]), "r"(a[3]), "r"(b[0]), "r"(b[1]));
}

__device__ __forceinline__ uint32_t smem_addr_u32(const void* p) {
    uint32_t a;
    asm("{ .reg .u64 t; cvta.to.shared.u64 t, %1; cvt.u32.u64 %0, t; }" : "=r"(a) : "l"(p));
    return a;
}

// ===========================================================================
// tf32 rounding pass (rna): dst = round(src)
// ===========================================================================
__global__ void __launch_bounds__(256)
round_tf32_kernel(const float4* __restrict__ src, float4* __restrict__ dst, int n4)
{
    int i = blockIdx.x * blockDim.x + threadIdx.x;
    if (i >= n4) return;
    float4 v = src[i];
    v.x = f2tf32f(v.x); v.y = f2tf32f(v.y);
    v.z = f2tf32f(v.z); v.w = f2tf32f(v.w);
    dst[i] = v;
}

// ===========================================================================
// tf32 tensor-core GEMM body: Y = X @ W^T + bias. Inputs pre-rounded to tf32.
// Tile 128x128, BK=32, 3-stage cp.async pipeline. 256 threads / 8 warps.
// ===========================================================================
#define TBM 128
#define TBN 128
#define TBK 32
#define LDS_ROW 36
#define MAT_FLOATS (TBM * LDS_ROW)          // 4608 floats per matrix per stage
#define STG_FLOATS (2 * MAT_FLOATS)         // 9216 floats per stage (A + B)
#define GSTAGES 3
#define G_SMEM_BYTES (GSTAGES * STG_FLOATS * 4)   // 110592

template <bool ROUND_OUT>
__device__ __forceinline__ void gemm_body(
    float* smem,
    const float* __restrict__ X, const float* __restrict__ W,
    const float* __restrict__ bias, float* __restrict__ Y,
    int bm, int bn)
{
    const int tid = threadIdx.x;
    const int wid = tid >> 5;
    const int lane = tid & 31;
    const int wm = (wid >> 2) * 64;
    const int wn = (wid & 3) * 32;
    const int lr = lane >> 2;
    const int lc = lane & 3;

    float acc[4][4][4];
#pragma unroll
    for (int i = 0; i < 4; i++)
#pragma unroll
        for (int j = 0; j < 4; j++)
#pragma unroll
            for (int r = 0; r < 4; r++) acc[i][j][r] = 0.f;

    // Per-thread load geometry (constant across stages)
    const int ld_row = tid >> 3;            // 0..31 (base row step 32)
    const int ld_seg = (tid & 7) * 4;       // 0,4,...,28

    auto issue_stage = [&](int kt, int buf) {
        const int k0 = kt * TBK;
        float* a_dst = smem + buf * STG_FLOATS;
        float* b_dst = a_dst + MAT_FLOATS;
#pragma unroll
        for (int l = 0; l < 4; l++) {
            int row = ld_row + l * 32;
            const float* src = X + (size_t)(bm + row) * DIM + k0 + ld_seg;
            uint32_t dst = smem_addr_u32(a_dst + row * LDS_ROW + ld_seg);
            asm volatile("cp.async.cg.shared.global [%0], [%1], 16;" :: "r"(dst), "l"(src));
        }
#pragma unroll
        for (int l = 0; l < 4; l++) {
            int row = ld_row + l * 32;
            const float* src = W + (size_t)(bn + row) * DIM + k0 + ld_seg;
            uint32_t dst = smem_addr_u32(b_dst + row * LDS_ROW + ld_seg);
            asm volatile("cp.async.cg.shared.global [%0], [%1], 16;" :: "r"(dst), "l"(src));
        }
        asm volatile("cp.async.commit_group;" ::: "memory");
    };

    const int n_kt = DIM / TBK;   // 32
    issue_stage(0, 0);
    issue_stage(1, 1);

    int buf = 0;
    for (int kt = 0; kt < n_kt; kt++) {
        if (kt + 2 < n_kt) {
            issue_stage(kt + 2, (kt + 2) % GSTAGES);
            asm volatile("cp.async.wait_group 2;" ::: "memory");
        } else if (kt + 1 < n_kt) {
            asm volatile("cp.async.wait_group 1;" ::: "memory");
        } else {
            asm volatile("cp.async.wait_group 0;" ::: "memory");
        }
        __syncthreads();

        const float* a_s = smem + buf * STG_FLOATS;
        const float* b_s = a_s + MAT_FLOATS;

#pragma unroll
        for (int ks = 0; ks < 4; ks++) {
            const int k = ks * 8 + lc;
            uint32_t af[4][4];
#pragma unroll
            for (int mt = 0; mt < 4; mt++) {
                const float* p = a_s + (wm + mt * 16 + lr) * LDS_ROW + k;
                af[mt][0] = __float_as_uint(p[0]);
                af[mt][1] = __float_as_uint(p[8 * LDS_ROW]);
                af[mt][2] = __float_as_uint(p[4]);
                af[mt][3] = __float_as_uint(p[8 * LDS_ROW + 4]);
            }
            uint32_t bf[4][2];
#pragma unroll
            for (int nt = 0; nt < 4; nt++) {
                const float* p = b_s + (wn + nt * 8 + lr) * LDS_ROW + k;
                bf[nt][0] = __float_as_uint(p[0]);
                bf[nt][1] = __float_as_uint(p[4]);
            }
#pragma unroll
            for (int mt = 0; mt < 4; mt++)
#pragma unroll
                for (int nt = 0; nt < 4; nt++)
                    mma1688(acc[mt][nt], af[mt], bf[nt]);
        }
        __syncthreads();
        if (++buf == GSTAGES) buf = 0;
    }

#pragma unroll
    for (int mt = 0; mt < 4; mt++) {
#pragma unroll
        for (int nt = 0; nt < 4; nt++) {
            const int row = bm + wm + mt * 16 + lr;
            const int col = bn + wn + nt * 8 + lc * 2;
            float2 bv = *(const float2*)(bias + col);
            float2 o0, o1;
            if (ROUND_OUT) {
                o0.x = f2tf32f(acc[mt][nt][0] + bv.x);
                o0.y = f2tf32f(acc[mt][nt][1] + bv.y);
                o1.x = f2tf32f(acc[mt][nt][2] + bv.x);
                o1.y = f2tf32f(acc[mt][nt][3] + bv.y);
            } else {
                o0.x = acc[mt][nt][0] + bv.x;
                o0.y = acc[mt][nt][1] + bv.y;
                o1.x = acc[mt][nt][2] + bv.x;
                o1.y = acc[mt][nt][3] + bv.y;
            }
            *(float2*)(Y + (size_t)row * DIM + col)       = o0;
            *(float2*)(Y + (size_t)(row + 8) * DIM + col) = o1;
        }
    }
}

// Fused Q/K/V projection: blockIdx.z selects weight/bias/output. Output tf32-rounded.
__global__ void __launch_bounds__(256, 2)
gemm_qkv_kernel(const float* __restrict__ X,
                const float* __restrict__ Wq, const float* __restrict__ bq, float* __restrict__ Qo,
                const float* __restrict__ Wk, const float* __restrict__ bk, float* __restrict__ Ko,
                const float* __restrict__ Wv, const float* __restrict__ bv, float* __restrict__ Vo)
{
    extern __shared__ float smem[];
    const int z = blockIdx.z;
    const float* W = (z == 0) ? Wq : (z == 1) ? Wk : Wv;
    const float* b = (z == 0) ? bq : (z == 1) ? bk : bv;
    float* Y       = (z == 0) ? Qo : (z == 1) ? Ko : Vo;
    gemm_body<true>(smem, X, W, b, Y, blockIdx.y * TBM, blockIdx.x * TBN);
}

// Output projection: no rounding of result.
__global__ void __launch_bounds__(256, 2)
gemm_o_kernel(const float* __restrict__ X, const float* __restrict__ W,
              const float* __restrict__ bias, float* __restrict__ Y)
{
    extern __shared__ float smem[];
    gemm_body<false>(smem, X, W, bias, Y, blockIdx.y * TBM, blockIdx.x * TBN);
}

// ===========================================================================
// Tensor-core flash attention (tf32 mma.sync).
// Grid: (SEQ/128, HEADS, BATCH). 256 threads = 8 warps, 16 query rows/warp.
// Inputs Q/K/V pre-rounded to tf32 by the projection epilogue.
// CTX output rounded to tf32 here (consumed by gemm_o).
// ===========================================================================
#define ABQ 128
#define ABKV 64
#define ALD 72
#define KV_TILE_FLOATS (ABKV * ALD)     // 4608
#define QP_FLOATS (ABQ * ALD)           // 9216
#define ATT_SMEM_BYTES ((4 * KV_TILE_FLOATS + QP_FLOATS) * 4)   // 110592

__global__ void __launch_bounds__(256, 2)
attn_tc_kernel(const float* __restrict__ Qg, const float* __restrict__ Kg,
               const float* __restrict__ Vg, float* __restrict__ Cg)
{
    extern __shared__ float smem[];
    float* Kb = smem;                       // [2][64][72]
    float* Vb = smem + 2 * KV_TILE_FLOATS;  // [2][64][72]
    float* QP = smem + 4 * KV_TILE_FLOATS;  // Q tile [128][72], later P scratch

    const int qt = blockIdx.x;
    const int h  = blockIdx.y;
    const int b  = blockIdx.z;
    const int tid = threadIdx.x;
    const int wid = tid >> 5;
    const int lane = tid & 31;
    const int lr = lane >> 2;
    const int lc = lane & 3;
    const int q0 = wid * 16;
    const size_t RS = HEADS * DK;   // 1024 gmem row stride

    const float* Qbase = Qg + ((size_t)(b * SEQ + qt * ABQ) * HEADS + h) * DK;
    const float* Kh = Kg + ((size_t)b * SEQ * HEADS + h) * DK;
    const float* Vh = Vg + ((size_t)b * SEQ * HEADS + h) * DK;

    // ---- group A: load Q tile (128 x 64) ----
#pragma unroll
    for (int l = 0; l < 8; l++) {
        int idx = tid + l * 256;
        int row = idx >> 4;
        int seg = (idx & 15) * 4;
        const float* src = Qbase + (size_t)row * RS + seg;
        uint32_t dst = smem_addr_u32(QP + row * ALD + seg);
        asm volatile("cp.async.cg.shared.global [%0], [%1], 16;" :: "r"(dst), "l"(src));
    }
    asm volatile("cp.async.commit_group;" ::: "memory");

    auto issue_kv = [&](int t, int buf) {
        const size_t s0 = (size_t)t * ABKV;
        float* kd = Kb + buf * KV_TILE_FLOATS;
        float* vd = Vb + buf * KV_TILE_FLOATS;
#pragma unroll
        for (int l = 0; l < 4; l++) {
            int idx = tid + l * 256;
            int row = idx >> 4;
            int seg = (idx & 15) * 4;
            const float* src = Kh + (s0 + row) * RS + seg;
            uint32_t dst = smem_addr_u32(kd + row * ALD + seg);
            asm volatile("cp.async.cg.shared.global [%0], [%1], 16;" :: "r"(dst), "l"(src));
        }
#pragma unroll
        for (int l = 0; l < 4; l++) {
            int idx = tid + l * 256;
            int row = idx >> 4;
            int seg = (idx & 15) * 4;
            const float* src = Vh + (s0 + row) * RS + seg;
            uint32_t dst = smem_addr_u32(vd + row * ALD + seg);
            asm volatile("cp.async.cg.shared.global [%0], [%1], 16;" :: "r"(dst), "l"(src));
        }
        asm volatile("cp.async.commit_group;" ::: "memory");
    };

    issue_kv(0, 0);                                       // group B
    asm volatile("cp.async.wait_group 1;" ::: "memory");  // Q (A) done
    __syncthreads();

    // ---- build Q fragments (pre-rounded tf32 bit patterns) ----
    uint32_t aq[8][4];
#pragma unroll
    for (int kk = 0; kk < 8; kk++) {
        const float* p = QP + (q0 + lr) * ALD + kk * 8 + lc;
        aq[kk][0] = __float_as_uint(p[0]);
        aq[kk][1] = __float_as_uint(p[8 * ALD]);
        aq[kk][2] = __float_as_uint(p[4]);
        aq[kk][3] = __float_as_uint(p[8 * ALD + 4]);
    }
    __syncthreads();
    // QP now becomes per-warp P scratch (each warp reuses its own 16 rows)
    float* Pw = QP + q0 * ALD;

    float oacc[8][4];
    float m_i[2] = {-INFINITY, -INFINITY};
    float l_i[2] = {0.f, 0.f};
#pragma unroll
    for (int nt = 0; nt < 8; nt++)
#pragma unroll
        for (int r = 0; r < 4; r++) oacc[nt][r] = 0.f;

    const int n_t = SEQ / ABKV;   // 32
    for (int t = 0; t < n_t; t++) {
        if (t + 1 < n_t) {
            issue_kv(t + 1, (t + 1) & 1);
            asm volatile("cp.async.wait_group 1;" ::: "memory");
        } else {
            asm volatile("cp.async.wait_group 0;" ::: "memory");
        }
        __syncthreads();

        const float* ks = Kb + (t & 1) * KV_TILE_FLOATS;
        const float* vs = Vb + (t & 1) * KV_TILE_FLOATS;

        // ---- S = Q @ K^T  (16 x 64 per warp) ----
        float sacc[8][4];
#pragma unroll
        for (int nt = 0; nt < 8; nt++)
#pragma unroll
            for (int r = 0; r < 4; r++) sacc[nt][r] = 0.f;

#pragma unroll
        for (int kk = 0; kk < 8; kk++) {
#pragma unroll
            for (int nt = 0; nt < 8; nt++) {
                const float* p = ks + (nt * 8 + lr) * ALD + kk * 8 + lc;
                uint32_t bk[2];
                bk[0] = __float_as_uint(p[0]);
                bk[1] = __float_as_uint(p[4]);
                mma1688(sacc[nt], aq[kk], bk);
            }
        }

        // ---- online softmax (scale applied post-mma; rows lr, lr+8) ----
#pragma unroll
        for (int j = 0; j < 2; j++) {
            float mx = -INFINITY;
#pragma unroll
            for (int nt = 0; nt < 8; nt++) {
                sacc[nt][2 * j]     *= 0.125f;
                sacc[nt][2 * j + 1] *= 0.125f;
                mx = fmaxf(mx, sacc[nt][2 * j]);
                mx = fmaxf(mx, sacc[nt][2 * j + 1]);
            }
            mx = fmaxf(mx, __shfl_xor_sync(0xffffffffu, mx, 1));
            mx = fmaxf(mx, __shfl_xor_sync(0xffffffffu, mx, 2));
            float m_new = fmaxf(m_i[j], mx);
            float corr = __expf(m_i[j] - m_new);
            float rs = 0.f;
#pragma unroll
            for (int nt = 0; nt < 8; nt++) {
                float p0 = __expf(sacc[nt][2 * j]     - m_new);
                float p1 = __expf(sacc[nt][2 * j + 1] - m_new);
                sacc[nt][2 * j]     = p0;
                sacc[nt][2 * j + 1] = p1;
                rs += p0 + p1;
            }
            rs += __shfl_xor_sync(0xffffffffu, rs, 1);
            rs += __shfl_xor_sync(0xffffffffu, rs, 2);
            l_i[j] = l_i[j] * corr + rs;
            m_i[j] = m_new;
#pragma unroll
            for (int nt = 0; nt < 8; nt++) {
                oacc[nt][2 * j]     *= corr;
                oacc[nt][2 * j + 1] *= corr;
            }
        }

        // ---- store P (rna-rounded) to warp-private smem ----
#pragma unroll
        for (int nt = 0; nt < 8; nt++) {
            float2 p01, p23;
            p01.x = f2tf32f(sacc[nt][0]); p01.y = f2tf32f(sacc[nt][1]);
            p23.x = f2tf32f(sacc[nt][2]); p23.y = f2tf32f(sacc[nt][3]);
            *(float2*)(Pw + lr * ALD + nt * 8 + 2 * lc)       = p01;
            *(float2*)(Pw + (lr + 8) * ALD + nt * 8 + 2 * lc) = p23;
        }
        __syncwarp();

        // ---- O += P @ V  (k over kv, n over dk) ----
#pragma unroll
        for (int kk = 0; kk < 8; kk++) {
            uint32_t ap[4];
            const float* pp = Pw + lr * ALD + kk * 8 + lc;
            ap[0] = __float_as_uint(pp[0]);
            ap[1] = __float_as_uint(pp[8 * ALD]);
            ap[2] = __float_as_uint(pp[4]);
            ap[3] = __float_as_uint(pp[8 * ALD + 4]);
#pragma unroll
            for (int nt = 0; nt < 8; nt++) {
                const float* vp = vs + (kk * 8 + lc) * ALD + nt * 8 + lr;
                uint32_t bv[2];
                bv[0] = __float_as_uint(vp[0]);
                bv[1] = __float_as_uint(vp[4 * ALD]);
                mma1688(oacc[nt], ap, bv);
            }
        }
        __syncthreads();
    }

    // ---- epilogue: normalize, round to tf32 (for gemm_o), write ctx ----
    float* Cbase = Cg + ((size_t)(b * SEQ + qt * ABQ) * HEADS + h) * DK;
    const float inv0 = 1.f / l_i[0];
    const float inv1 = 1.f / l_i[1];
    const int r0g = q0 + lr;
    const int r1g = q0 + lr + 8;
#pragma unroll
    for (int nt = 0; nt < 8; nt++) {
        const int col = nt * 8 + 2 * lc;
        float2 o0, o1;
        o0.x = f2tf32f(oacc[nt][0] * inv0); o0.y = f2tf32f(oacc[nt][1] * inv0);
        o1.x = f2tf32f(oacc[nt][2] * inv1); o1.y = f2tf32f(oacc[nt][3] * inv1);
        *(float2*)(Cbase + (size_t)r0g * RS + col) = o0;
        *(float2*)(Cbase + (size_t)r1g * RS + col) = o1;
    }
}

// ===========================================================================
// Launch
// ===========================================================================
extern "C" void kernel_launch(void* const* d_in, const int* in_sizes, int n_in,
                              void* d_out, int out_size)
{
    const float* X  = (const float*)d_in[0];
    const float* Wq = (const float*)d_in[1];
    const float* bq = (const float*)d_in[2];
    const float* Wk = (const float*)d_in[3];
    const float* bk = (const float*)d_in[4];
    const float* Wv = (const float*)d_in[5];
    const float* bv = (const float*)d_in[6];
    const float* Wo = (const float*)d_in[7];
    const float* bo = (const float*)d_in[8];

    float *Qp, *Kp, *Vp, *Cp, *Xr, *Wqr, *Wkr, *Wvr, *Wor;
    cudaGetSymbolAddress((void**)&Qp, g_Q);
    cudaGetSymbolAddress((void**)&Kp, g_K);
    cudaGetSymbolAddress((void**)&Vp, g_V);
    cudaGetSymbolAddress((void**)&Cp, g_CTX);
    cudaGetSymbolAddress((void**)&Xr, g_Xr);
    cudaGetSymbolAddress((void**)&Wqr, g_Wqr);
    cudaGetSymbolAddress((void**)&Wkr, g_Wkr);
    cudaGetSymbolAddress((void**)&Wvr, g_Wvr);
    cudaGetSymbolAddress((void**)&Wor, g_Wor);

    static bool attr_set = false;
    if (!attr_set) {
        cudaFuncSetAttribute(gemm_qkv_kernel,
                             cudaFuncAttributeMaxDynamicSharedMemorySize, G_SMEM_BYTES);
        cudaFuncSetAttribute(gemm_o_kernel,
                             cudaFuncAttributeMaxDynamicSharedMemorySize, G_SMEM_BYTES);
        cudaFuncSetAttribute(attn_tc_kernel,
                             cudaFuncAttributeMaxDynamicSharedMemorySize, ATT_SMEM_BYTES);
        attr_set = true;
    }

    const int xn4 = M_TOTAL * DIM / 4;   // 2097152
    const int wn4 = DIM * DIM / 4;       // 262144

    // Pre-round inputs to tf32 (hoists all mainloop cvts)
    round_tf32_kernel<<<(xn4 + 255) / 256, 256>>>((const float4*)X,  (float4*)Xr,  xn4);
    round_tf32_kernel<<<(wn4 + 255) / 256, 256>>>((const float4*)Wq, (float4*)Wqr, wn4);
    round_tf32_kernel<<<(wn4 + 255) / 256, 256>>>((const float4*)Wk, (float4*)Wkr, wn4);
    round_tf32_kernel<<<(wn4 + 255) / 256, 256>>>((const float4*)Wv, (float4*)Wvr, wn4);
    round_tf32_kernel<<<(wn4 + 255) / 256, 256>>>((const float4*)Wo, (float4*)Wor, wn4);

    dim3 qkv_grid(DIM / TBN, M_TOTAL / TBM, 3);   // (8, 64, 3)
    gemm_qkv_kernel<<<qkv_grid, 256, G_SMEM_BYTES>>>(Xr, Wqr, bq, Qp,
                                                     Wkr, bk, Kp,
                                                     Wvr, bv, Vp);

    attn_tc_kernel<<<dim3(SEQ / ABQ, HEADS, BATCH), 256, ATT_SMEM_BYTES>>>(Qp, Kp, Vp, Cp);

    dim3 o_grid(DIM / TBN, M_TOTAL / TBM);        // (8, 64)
    gemm_o_kernel<<<o_grid, 256, G_SMEM_BYTES>>>(Cp, Wor, bo, (float*)d_out);
}

// round 7
// speedup vs baseline: 4.4278x; 1.1744x over previous
#include <cuda_runtime.h>
#include <cstdint>
#include <math.h>

#define BATCH 4
#define SEQ 2048
#define DIM 1024
#define HEADS 16
#define DK 64
#define M_TOTAL (BATCH * SEQ)   // 8192

// Scratch buffers (device globals; no allocation allowed)
__device__ float g_Q[M_TOTAL * DIM];
__device__ float g_K[M_TOTAL * DIM];
__device__ float g_Vt[M_TOTAL * DIM];    // V stored head-transposed: [b][h][dk][s]
__device__ float g_CTX[M_TOTAL * DIM];
__device__ float g_Xr[M_TOTAL * DIM];    // tf32-rounded activations
__device__ float g_Wqr[DIM * DIM];
__device__ float g_Wkr[DIM * DIM];
__device__ float g_Wvr[DIM * DIM];
__device__ float g_Wor[DIM * DIM];

// ===========================================================================
// Helpers
// ===========================================================================
__device__ __forceinline__ float f2tf32f(float x) {
    uint32_t r;
    asm("cvt.rna.tf32.f32 %0, %1;" : "=r"(r) : "f"(x));
    return __uint_as_float(r);
}

__device__ __forceinline__ void mma1688(float* d, const uint32_t* a, const uint32_t* b) {
    asm volatile(
        "mma.sync.aligned.m16n8k8.row.col.f32.tf32.tf32.f32 "
        "{%0,%1,%2,%3}, {%4,%5,%6,%7}, {%8,%9}, {%0,%1,%2,%3};"
        : "+f"(d[0]), "+f"(d[1]), "+f"(d[2]), "+f"(d[3])
        : "r"(a[0]), "r"(a[1]), "r"(a[2]), "r"(a[3]), "r"(b[0]), "r"(b[1]));
}

// ldmatrix x4: 4 8x8 b16-matrices (= 4 8(row)x4(word) fp32 quadrants).
// Lane l supplies row (l%8) of matrix (l/8); result reg j of lane l is
// word (row l/4, col l%4) of matrix j — exactly the tf32 fragment layout.
__device__ __forceinline__ void ldsm_x4(uint32_t* r, uint32_t addr) {
    asm volatile("ldmatrix.sync.aligned.m8n8.x4.shared.b16 {%0,%1,%2,%3}, [%4];"
        : "=r"(r[0]), "=r"(r[1]), "=r"(r[2]), "=r"(r[3]) : "r"(addr));
}

__device__ __forceinline__ uint32_t smem_addr_u32(const void* p) {
    uint32_t a;
    asm("{ .reg .u64 t; cvta.to.shared.u64 t, %1; cvt.u32.u64 %0, t; }" : "=r"(a) : "l"(p));
    return a;
}

// ===========================================================================
// Merged tf32 rounding pass: X (xn4) then 4 weights (wn4 each)
// xn4 = 2^21, wn4 = 2^18 -> pure shifts
// ===========================================================================
#define XN4 (M_TOTAL * DIM / 4)   // 2097152 = 2^21
#define WN4 (DIM * DIM / 4)       // 262144  = 2^18

__global__ void __launch_bounds__(256)
round_all_kernel(const float4* __restrict__ X,  float4* __restrict__ Xr,
                 const float4* __restrict__ Wq, float4* __restrict__ Wqr,
                 const float4* __restrict__ Wk, float4* __restrict__ Wkr,
                 const float4* __restrict__ Wv, float4* __restrict__ Wvr,
                 const float4* __restrict__ Wo, float4* __restrict__ Wor)
{
    int i = blockIdx.x * blockDim.x + threadIdx.x;
    const float4* src;
    float4* dst;
    int k;
    if (i < XN4) {
        src = X; dst = Xr; k = i;
    } else {
        int j = i - XN4;
        int w = j >> 18;
        k = j & (WN4 - 1);
        src = (w == 0) ? Wq : (w == 1) ? Wk : (w == 2) ? Wv : Wo;
        dst = (w == 0) ? Wqr : (w == 1) ? Wkr : (w == 2) ? Wvr : Wor;
    }
    float4 v = src[k];
    v.x = f2tf32f(v.x); v.y = f2tf32f(v.y);
    v.z = f2tf32f(v.z); v.w = f2tf32f(v.w);
    dst[k] = v;
}

// ===========================================================================
// tf32 tensor-core GEMM body: Y = X @ W^T + bias. Inputs pre-rounded to tf32.
// Tile 128x128, BK=32, 3-stage cp.async pipeline, ldmatrix fragment loads.
// If Yt != nullptr, the output is written head-transposed ([b][h][dk][s]).
// ===========================================================================
#define TBM 128
#define TBN 128
#define TBK 32
#define LDS_ROW 36
#define MAT_FLOATS (TBM * LDS_ROW)          // 4608
#define STG_FLOATS (2 * MAT_FLOATS)         // 9216
#define GSTAGES 3
#define G_SMEM_BYTES (GSTAGES * STG_FLOATS * 4)   // 110592

template <bool ROUND_OUT>
__device__ __forceinline__ void gemm_body(
    float* smem,
    const float* __restrict__ X, const float* __restrict__ W,
    const float* __restrict__ bias, float* __restrict__ Y, float* __restrict__ Yt,
    int bm, int bn)
{
    const int tid = threadIdx.x;
    const int wid = tid >> 5;
    const int lane = tid & 31;
    const int wm = (wid >> 2) * 64;
    const int wn = (wid & 3) * 32;
    const int lr = lane >> 2;
    const int lc = lane & 3;
    const int lm = lane >> 3;     // ldmatrix: which of the 4 matrices
    const int l8 = lane & 7;      // ldmatrix: row within matrix

    const uint32_t s_u32 = smem_addr_u32(smem);

    // Precomputed per-thread ldmatrix lane addresses (bytes, stage-relative)
    uint32_t offA[4], offB[2];
#pragma unroll
    for (int mt = 0; mt < 4; mt++)
        offA[mt] = (uint32_t)(((wm + mt * 16 + (lm & 1) * 8 + l8) * LDS_ROW + (lm >> 1) * 4) * 4);
#pragma unroll
    for (int p = 0; p < 2; p++)
        offB[p] = (uint32_t)(((wn + p * 16 + (lm >> 1) * 8 + l8) * LDS_ROW + (lm & 1) * 4) * 4);

    float acc[4][4][4];
#pragma unroll
    for (int i = 0; i < 4; i++)
#pragma unroll
        for (int j = 0; j < 4; j++)
#pragma unroll
            for (int r = 0; r < 4; r++) acc[i][j][r] = 0.f;

    const int ld_row = tid >> 3;
    const int ld_seg = (tid & 7) * 4;

    auto issue_stage = [&](int kt, int buf) {
        const int k0 = kt * TBK;
        float* a_dst = smem + buf * STG_FLOATS;
        float* b_dst = a_dst + MAT_FLOATS;
#pragma unroll
        for (int l = 0; l < 4; l++) {
            int row = ld_row + l * 32;
            const float* src = X + (size_t)(bm + row) * DIM + k0 + ld_seg;
            uint32_t dst = smem_addr_u32(a_dst + row * LDS_ROW + ld_seg);
            asm volatile("cp.async.cg.shared.global [%0], [%1], 16;" :: "r"(dst), "l"(src));
        }
#pragma unroll
        for (int l = 0; l < 4; l++) {
            int row = ld_row + l * 32;
            const float* src = W + (size_t)(bn + row) * DIM + k0 + ld_seg;
            uint32_t dst = smem_addr_u32(b_dst + row * LDS_ROW + ld_seg);
            asm volatile("cp.async.cg.shared.global [%0], [%1], 16;" :: "r"(dst), "l"(src));
        }
        asm volatile("cp.async.commit_group;" ::: "memory");
    };

    const int n_kt = DIM / TBK;   // 32
    issue_stage(0, 0);
    issue_stage(1, 1);

    int buf = 0;
    for (int kt = 0; kt < n_kt; kt++) {
        if (kt + 2 < n_kt) {
            issue_stage(kt + 2, (kt + 2) % GSTAGES);
            asm volatile("cp.async.wait_group 2;" ::: "memory");
        } else if (kt + 1 < n_kt) {
            asm volatile("cp.async.wait_group 1;" ::: "memory");
        } else {
            asm volatile("cp.async.wait_group 0;" ::: "memory");
        }
        __syncthreads();

        const uint32_t a_base = s_u32 + buf * (STG_FLOATS * 4);
        const uint32_t b_base = a_base + MAT_FLOATS * 4;

#pragma unroll
        for (int ks = 0; ks < 4; ks++) {
            const uint32_t ko = ks * 32;   // 8 floats
            uint32_t af[4][4], bf[2][4];
#pragma unroll
            for (int mt = 0; mt < 4; mt++) ldsm_x4(af[mt], a_base + offA[mt] + ko);
#pragma unroll
            for (int p = 0; p < 2; p++)    ldsm_x4(bf[p],  b_base + offB[p] + ko);
#pragma unroll
            for (int mt = 0; mt < 4; mt++)
#pragma unroll
                for (int nt = 0; nt < 4; nt++)
                    mma1688(acc[mt][nt], af[mt], &bf[nt >> 1][(nt & 1) * 2]);
        }
        __syncthreads();
        if (++buf == GSTAGES) buf = 0;
    }

#pragma unroll
    for (int mt = 0; mt < 4; mt++) {
#pragma unroll
        for (int nt = 0; nt < 4; nt++) {
            const int row = bm + wm + mt * 16 + lr;
            const int col = bn + wn + nt * 8 + lc * 2;
            float2 bv = *(const float2*)(bias + col);
            float2 o0, o1;
            if (ROUND_OUT) {
                o0.x = f2tf32f(acc[mt][nt][0] + bv.x);
                o0.y = f2tf32f(acc[mt][nt][1] + bv.y);
                o1.x = f2tf32f(acc[mt][nt][2] + bv.x);
                o1.y = f2tf32f(acc[mt][nt][3] + bv.y);
            } else {
                o0.x = acc[mt][nt][0] + bv.x;
                o0.y = acc[mt][nt][1] + bv.y;
                o1.x = acc[mt][nt][2] + bv.x;
                o1.y = acc[mt][nt][3] + bv.y;
            }
            if (Yt) {
                // head-transposed: Yt[((b*H + h)*DK + d)*SEQ + s]
                const size_t base = ((size_t)(row >> 11) * HEADS + (col >> 6)) * DK;
                const int s0 = row & 2047;
                Yt[(base + (col & 63)) * SEQ + s0]           = o0.x;
                Yt[(base + ((col & 63) + 1)) * SEQ + s0]     = o0.y;
                Yt[(base + (col & 63)) * SEQ + s0 + 8]       = o1.x;
                Yt[(base + ((col & 63) + 1)) * SEQ + s0 + 8] = o1.y;
            } else {
                *(float2*)(Y + (size_t)row * DIM + col)       = o0;
                *(float2*)(Y + (size_t)(row + 8) * DIM + col) = o1;
            }
        }
    }
}

// Fused Q/K/V projection: z selects weight/bias/output. Output tf32-rounded.
// z == 2 (V) is stored head-transposed for ldmatrix-friendly attention loads.
__global__ void __launch_bounds__(256, 2)
gemm_qkv_kernel(const float* __restrict__ X,
                const float* __restrict__ Wq, const float* __restrict__ bq, float* __restrict__ Qo,
                const float* __restrict__ Wk, const float* __restrict__ bk, float* __restrict__ Ko,
                const float* __restrict__ Wv, const float* __restrict__ bv, float* __restrict__ Vto)
{
    extern __shared__ float smem[];
    const int z = blockIdx.z;
    const float* W = (z == 0) ? Wq : (z == 1) ? Wk : Wv;
    const float* b = (z == 0) ? bq : (z == 1) ? bk : bv;
    float* Y  = (z == 0) ? Qo : (z == 1) ? Ko : nullptr;
    float* Yt = (z == 2) ? Vto : nullptr;
    gemm_body<true>(smem, X, W, b, Y, Yt, blockIdx.y * TBM, blockIdx.x * TBN);
}

// Output projection: plain fp32 output.
__global__ void __launch_bounds__(256, 2)
gemm_o_kernel(const float* __restrict__ X, const float* __restrict__ W,
              const float* __restrict__ bias, float* __restrict__ Y)
{
    extern __shared__ float smem[];
    gemm_body<false>(smem, X, W, bias, Y, nullptr, blockIdx.y * TBM, blockIdx.x * TBN);
}

// ===========================================================================
// Tensor-core flash attention (tf32 mma.sync + ldmatrix fragment loads).
// Grid: (SEQ/128, HEADS, BATCH). 256 threads = 8 warps, 16 query rows/warp.
// K tile [kv=64][dk=64], V tile [dk=64][kv=64] (from head-transposed g_Vt).
// ALD = 68 floats (272B) -> conflict-free ldmatrix row gathers.
// ===========================================================================
#define ABQ 128
#define ABKV 64
#define ALD 68
#define KV_TILE_FLOATS (ABKV * ALD)     // 4352
#define QP_FLOATS (ABQ * ALD)           // 8704
#define ATT_SMEM_BYTES ((4 * KV_TILE_FLOATS + QP_FLOATS) * 4)   // 104448

__global__ void __launch_bounds__(256, 2)
attn_tc_kernel(const float* __restrict__ Qg, const float* __restrict__ Kg,
               const float* __restrict__ Vtg, float* __restrict__ Cg)
{
    extern __shared__ float smem[];
    float* Kb = smem;                       // [2][64][68]
    float* Vb = smem + 2 * KV_TILE_FLOATS;  // [2][64][68]
    float* QP = smem + 4 * KV_TILE_FLOATS;  // Q tile [128][68], later P scratch

    const int qt = blockIdx.x;
    const int h  = blockIdx.y;
    const int b  = blockIdx.z;
    const int tid = threadIdx.x;
    const int wid = tid >> 5;
    const int lane = tid & 31;
    const int lr = lane >> 2;
    const int lc = lane & 3;
    const int lm = lane >> 3;
    const int l8 = lane & 7;
    const int q0 = wid * 16;
    const size_t RS = HEADS * DK;   // 1024

    const uint32_t s_u32 = smem_addr_u32(smem);

    // ldmatrix lane offsets (bytes). K and V tiles share geometry.
    uint32_t offKV[4];
#pragma unroll
    for (int p = 0; p < 4; p++)
        offKV[p] = (uint32_t)((((2 * p + (lm >> 1)) * 8 + l8) * ALD + (lm & 1) * 4) * 4);
    const uint32_t offP = (uint32_t)((((lm & 1) * 8 + l8) * ALD + (lm >> 1) * 4) * 4);
    const uint32_t p_base = s_u32 + (4 * KV_TILE_FLOATS + q0 * ALD) * 4;

    const float* Qbase = Qg + ((size_t)(b * SEQ + qt * ABQ) * HEADS + h) * DK;
    const float* Kh  = Kg  + ((size_t)b * SEQ * HEADS + h) * DK;
    const float* Vth = Vtg + ((size_t)(b * HEADS + h) * DK) * SEQ;

    // ---- group A: load Q tile (128 x 64) ----
#pragma unroll
    for (int l = 0; l < 8; l++) {
        int idx = tid + l * 256;
        int row = idx >> 4;
        int seg = (idx & 15) * 4;
        const float* src = Qbase + (size_t)row * RS + seg;
        uint32_t dst = smem_addr_u32(QP + row * ALD + seg);
        asm volatile("cp.async.cg.shared.global [%0], [%1], 16;" :: "r"(dst), "l"(src));
    }
    asm volatile("cp.async.commit_group;" ::: "memory");

    auto issue_kv = [&](int t, int bufi) {
        float* kd = Kb + bufi * KV_TILE_FLOATS;
        float* vd = Vb + bufi * KV_TILE_FLOATS;
        const size_t s0 = (size_t)t * ABKV;
#pragma unroll
        for (int l = 0; l < 4; l++) {
            int idx = tid + l * 256;
            int row = idx >> 4;
            int seg = (idx & 15) * 4;
            const float* src = Kh + (s0 + row) * RS + seg;   // row = kv, seg = dk
            uint32_t dst = smem_addr_u32(kd + row * ALD + seg);
            asm volatile("cp.async.cg.shared.global [%0], [%1], 16;" :: "r"(dst), "l"(src));
        }
#pragma unroll
        for (int l = 0; l < 4; l++) {
            int idx = tid + l * 256;
            int row = idx >> 4;                               // row = dk
            int seg = (idx & 15) * 4;                         // seg = kv offset
            const float* src = Vth + (size_t)row * SEQ + s0 + seg;
            uint32_t dst = smem_addr_u32(vd + row * ALD + seg);
            asm volatile("cp.async.cg.shared.global [%0], [%1], 16;" :: "r"(dst), "l"(src));
        }
        asm volatile("cp.async.commit_group;" ::: "memory");
    };

    issue_kv(0, 0);
    asm volatile("cp.async.wait_group 1;" ::: "memory");  // Q done
    __syncthreads();

    // ---- build Q fragments (pre-rounded tf32 bit patterns) ----
    uint32_t aq[8][4];
#pragma unroll
    for (int kk = 0; kk < 8; kk++) {
        const float* p = QP + (q0 + lr) * ALD + kk * 8 + lc;
        aq[kk][0] = __float_as_uint(p[0]);
        aq[kk][1] = __float_as_uint(p[8 * ALD]);
        aq[kk][2] = __float_as_uint(p[4]);
        aq[kk][3] = __float_as_uint(p[8 * ALD + 4]);
    }
    __syncthreads();
    float* Pw = QP + q0 * ALD;   // per-warp P scratch

    float oacc[8][4];
    float m_i[2] = {-INFINITY, -INFINITY};
    float l_i[2] = {0.f, 0.f};
#pragma unroll
    for (int nt = 0; nt < 8; nt++)
#pragma unroll
        for (int r = 0; r < 4; r++) oacc[nt][r] = 0.f;

    const int n_t = SEQ / ABKV;   // 32
    for (int t = 0; t < n_t; t++) {
        if (t + 1 < n_t) {
            issue_kv(t + 1, (t + 1) & 1);
            asm volatile("cp.async.wait_group 1;" ::: "memory");
        } else {
            asm volatile("cp.async.wait_group 0;" ::: "memory");
        }
        __syncthreads();

        const uint32_t k_base = s_u32 + ((t & 1) * KV_TILE_FLOATS) * 4;
        const uint32_t v_base = s_u32 + ((2 + (t & 1)) * KV_TILE_FLOATS) * 4;

        // ---- S = Q @ K^T  (16 x 64 per warp) ----
        float sacc[8][4];
#pragma unroll
        for (int nt = 0; nt < 8; nt++)
#pragma unroll
            for (int r = 0; r < 4; r++) sacc[nt][r] = 0.f;

#pragma unroll
        for (int kk = 0; kk < 8; kk++) {
            const uint32_t ko = kk * 32;
            uint32_t bk[4][4];
#pragma unroll
            for (int p = 0; p < 4; p++) ldsm_x4(bk[p], k_base + offKV[p] + ko);
#pragma unroll
            for (int nt = 0; nt < 8; nt++)
                mma1688(sacc[nt], aq[kk], &bk[nt >> 1][(nt & 1) * 2]);
        }

        // ---- online softmax (scale post-mma; rows lr, lr+8) ----
#pragma unroll
        for (int j = 0; j < 2; j++) {
            float mx = -INFINITY;
#pragma unroll
            for (int nt = 0; nt < 8; nt++) {
                sacc[nt][2 * j]     *= 0.125f;
                sacc[nt][2 * j + 1] *= 0.125f;
                mx = fmaxf(mx, sacc[nt][2 * j]);
                mx = fmaxf(mx, sacc[nt][2 * j + 1]);
            }
            mx = fmaxf(mx, __shfl_xor_sync(0xffffffffu, mx, 1));
            mx = fmaxf(mx, __shfl_xor_sync(0xffffffffu, mx, 2));
            float m_new = fmaxf(m_i[j], mx);
            float corr = __expf(m_i[j] - m_new);
            float rs = 0.f;
#pragma unroll
            for (int nt = 0; nt < 8; nt++) {
                float p0 = __expf(sacc[nt][2 * j]     - m_new);
                float p1 = __expf(sacc[nt][2 * j + 1] - m_new);
                sacc[nt][2 * j]     = p0;
                sacc[nt][2 * j + 1] = p1;
                rs += p0 + p1;
            }
            rs += __shfl_xor_sync(0xffffffffu, rs, 1);
            rs += __shfl_xor_sync(0xffffffffu, rs, 2);
            l_i[j] = l_i[j] * corr + rs;
            m_i[j] = m_new;
#pragma unroll
            for (int nt = 0; nt < 8; nt++) {
                oacc[nt][2 * j]     *= corr;
                oacc[nt][2 * j + 1] *= corr;
            }
        }

        // ---- store P (rna-rounded) to warp-private smem ----
#pragma unroll
        for (int nt = 0; nt < 8; nt++) {
            float2 p01, p23;
            p01.x = f2tf32f(sacc[nt][0]); p01.y = f2tf32f(sacc[nt][1]);
            p23.x = f2tf32f(sacc[nt][2]); p23.y = f2tf32f(sacc[nt][3]);
            *(float2*)(Pw + lr * ALD + nt * 8 + 2 * lc)       = p01;
            *(float2*)(Pw + (lr + 8) * ALD + nt * 8 + 2 * lc) = p23;
        }
        __syncwarp();

        // ---- O += P @ V ----
#pragma unroll
        for (int kk = 0; kk < 8; kk++) {
            const uint32_t ko = kk * 32;
            uint32_t ap[4];
            ldsm_x4(ap, p_base + offP + ko);
            uint32_t bv[4][4];
#pragma unroll
            for (int p = 0; p < 4; p++) ldsm_x4(bv[p], v_base + offKV[p] + ko);
#pragma unroll
            for (int nt = 0; nt < 8; nt++)
                mma1688(oacc[nt], ap, &bv[nt >> 1][(nt & 1) * 2]);
        }
        __syncthreads();
    }

    // ---- epilogue: normalize, round to tf32 (for gemm_o), write ctx ----
    float* Cbase = Cg + ((size_t)(b * SEQ + qt * ABQ) * HEADS + h) * DK;
    const float inv0 = 1.f / l_i[0];
    const float inv1 = 1.f / l_i[1];
    const int r0g = q0 + lr;
    const int r1g = q0 + lr + 8;
#pragma unroll
    for (int nt = 0; nt < 8; nt++) {
        const int col = nt * 8 + 2 * lc;
        float2 o0, o1;
        o0.x = f2tf32f(oacc[nt][0] * inv0); o0.y = f2tf32f(oacc[nt][1] * inv0);
        o1.x = f2tf32f(oacc[nt][2] * inv1); o1.y = f2tf32f(oacc[nt][3] * inv1);
        *(float2*)(Cbase + (size_t)r0g * RS + col) = o0;
        *(float2*)(Cbase + (size_t)r1g * RS + col) = o1;
    }
}

// ===========================================================================
// Launch
// ===========================================================================
extern "C" void kernel_launch(void* const* d_in, const int* in_sizes, int n_in,
                              void* d_out, int out_size)
{
    const float* X  = (const float*)d_in[0];
    const float* Wq = (const float*)d_in[1];
    const float* bq = (const float*)d_in[2];
    const float* Wk = (const float*)d_in[3];
    const float* bk = (const float*)d_in[4];
    const float* Wv = (const float*)d_in[5];
    const float* bv = (const float*)d_in[6];
    const float* Wo = (const float*)d_in[7];
    const float* bo = (const float*)d_in[8];

    float *Qp, *Kp, *Vtp, *Cp, *Xr, *Wqr, *Wkr, *Wvr, *Wor;
    cudaGetSymbolAddress((void**)&Qp,  g_Q);
    cudaGetSymbolAddress((void**)&Kp,  g_K);
    cudaGetSymbolAddress((void**)&Vtp, g_Vt);
    cudaGetSymbolAddress((void**)&Cp,  g_CTX);
    cudaGetSymbolAddress((void**)&Xr,  g_Xr);
    cudaGetSymbolAddress((void**)&Wqr, g_Wqr);
    cudaGetSymbolAddress((void**)&Wkr, g_Wkr);
    cudaGetSymbolAddress((void**)&Wvr, g_Wvr);
    cudaGetSymbolAddress((void**)&Wor, g_Wor);

    static bool attr_set = false;
    if (!attr_set) {
        cudaFuncSetAttribute(gemm_qkv_kernel,
                             cudaFuncAttributeMaxDynamicSharedMemorySize, G_SMEM_BYTES);
        cudaFuncSetAttribute(gemm_o_kernel,
                             cudaFuncAttributeMaxDynamicSharedMemorySize, G_SMEM_BYTES);
        cudaFuncSetAttribute(attn_tc_kernel,
                             cudaFuncAttributeMaxDynamicSharedMemorySize, ATT_SMEM_BYTES);
        attr_set = true;
    }

    // Pre-round X + all weights to tf32 in ONE launch
    const int total4 = XN4 + 4 * WN4;   // 3145728
    round_all_kernel<<<total4 / 256, 256>>>(
        (const float4*)X,  (float4*)Xr,
        (const float4*)Wq, (float4*)Wqr,
        (const float4*)Wk, (float4*)Wkr,
        (const float4*)Wv, (float4*)Wvr,
        (const float4*)Wo, (float4*)Wor);

    dim3 qkv_grid(DIM / TBN, M_TOTAL / TBM, 3);   // (8, 64, 3)
    gemm_qkv_kernel<<<qkv_grid, 256, G_SMEM_BYTES>>>(Xr, Wqr, bq, Qp,
                                                     Wkr, bk, Kp,
                                                     Wvr, bv, Vtp);

    attn_tc_kernel<<<dim3(SEQ / ABQ, HEADS, BATCH), 256, ATT_SMEM_BYTES>>>(Qp, Kp, Vtp, Cp);

    dim3 o_grid(DIM / TBN, M_TOTAL / TBM);        // (8, 64)
    gemm_o_kernel<<<o_grid, 256, G_SMEM_BYTES>>>(Cp, Wor, bo, (float*)d_out);
}